// round 6
// baseline (speedup 1.0000x reference)
#include <cuda_runtime.h>
#include <cuda_bf16.h>
#include <cstdint>

// ---------------------------------------------------------------------------
// TernaryCNN v4:
//  - implicit-GEMM convs, split-bf16 (hi/lo) activations, {-1,0,+1} weights
//  - activations stored PRE-PACKED as (hi,lo) uint32 by the pool epilogue;
//    GEMM gather is a bare predicated load (no per-tap conversion)
//  - BN batch statistics fused into the GEMM epilogue (deterministic slots)
//  - FC1 ternary stats fused into the FC1 GEMM pass
// ---------------------------------------------------------------------------

#define N_BATCH 32

// -------------------- device scratch (static, no allocs) -------------------
__device__ float g_conv[33554432];        // conv out C-major [co][n][h][w]
__device__ uint32_t g_pool[8388608];      // pooled NCHW, packed (hi,lo)
__device__ uint32_t g_xpack[2097152];     // packed layer-1 input [32][4][16384]
__device__ uint32_t g_A1[2048];           // packed tern weights 64 x 32
__device__ uint32_t g_A2[73728];          // 128 x 576
__device__ uint32_t g_A3[294912];         // 256 x 1152
__device__ uint32_t g_A4[1179648];        // 512 x 2304
__device__ float g_fc1[32 * 1024];
__device__ float g_fc1part[16 * 32 * 1024];
__device__ float g_part1[512];
__device__ float g_part2[512];
__device__ float g_scal[32];              // 8 slots x 4: [0]=delta [1]=alpha [2]=mean
__device__ float g_bnp1[262144];          // [co][bx] partial sums (max 64*4096)
__device__ float g_bnp2[262144];
__device__ float g_bnscale[512];
__device__ float g_bnshift[512];

// ----------------------------- helpers -------------------------------------
__device__ __forceinline__ uint32_t pack_split(float x) {
    __nv_bfloat16 h = __float2bfloat16_rn(x);
    float hf = __bfloat162float(h);
    __nv_bfloat16 l = __float2bfloat16_rn(x - hf);
    return ((uint32_t)__bfloat16_as_ushort(l) << 16) | (uint32_t)__bfloat16_as_ushort(h);
}
__device__ __forceinline__ float unpack_split(uint32_t u) {
    __nv_bfloat16 h = __ushort_as_bfloat16((unsigned short)(u & 0xffff));
    __nv_bfloat16 l = __ushort_as_bfloat16((unsigned short)(u >> 16));
    return __bfloat162float(h) + __bfloat162float(l);
}

// ----------------------------- ternarize stats ------------------------------
__global__ void abs_sum_kernel(const float* __restrict__ w, long n, float* __restrict__ part) {
    __shared__ float sh[256];
    float a = 0.f;
    const long stride = (long)gridDim.x * 256;
    for (long i = (long)blockIdx.x * 256 + threadIdx.x; i < n; i += stride)
        a += fabsf(w[i]);
    sh[threadIdx.x] = a; __syncthreads();
    for (int o = 128; o > 0; o >>= 1) {
        if (threadIdx.x < o) sh[threadIdx.x] += sh[threadIdx.x + o];
        __syncthreads();
    }
    if (threadIdx.x == 0) part[blockIdx.x] = sh[0];
}

__global__ void delta_final_kernel(const float* __restrict__ part, int nb, float inv_n,
                                   float* __restrict__ scal) {
    __shared__ float sh[256];
    float a = 0.f;
    for (int i = threadIdx.x; i < nb; i += 256) a += part[i];
    sh[threadIdx.x] = a; __syncthreads();
    for (int o = 128; o > 0; o >>= 1) {
        if (threadIdx.x < o) sh[threadIdx.x] += sh[threadIdx.x + o];
        __syncthreads();
    }
    if (threadIdx.x == 0) {
        float mean = sh[0] * inv_n;
        scal[0] = 0.7f * mean;
        scal[2] = mean;
    }
}

__global__ void masked_sum_kernel(const float* __restrict__ w, long n, const float* __restrict__ scal,
                                  float* __restrict__ p1, float* __restrict__ p2) {
    __shared__ float sh1[256], sh2[256];
    const float delta = scal[0];
    const long stride = (long)gridDim.x * 256;
    float s = 0.f, c = 0.f;
    for (long i = (long)blockIdx.x * 256 + threadIdx.x; i < n; i += stride) {
        float v = fabsf(w[i]);
        if (v > delta) { s += v; c += 1.f; }
    }
    sh1[threadIdx.x] = s; sh2[threadIdx.x] = c; __syncthreads();
    for (int o = 128; o > 0; o >>= 1) {
        if (threadIdx.x < o) { sh1[threadIdx.x] += sh1[threadIdx.x + o]; sh2[threadIdx.x] += sh2[threadIdx.x + o]; }
        __syncthreads();
    }
    if (threadIdx.x == 0) { p1[blockIdx.x] = sh1[0]; p2[blockIdx.x] = sh2[0]; }
}

__global__ void alpha_final_kernel(const float* __restrict__ p1, const float* __restrict__ p2,
                                   int cnt, float* __restrict__ scal) {
    __shared__ float sh1[256], sh2[256];
    float s = 0.f, c = 0.f;
    for (int i = threadIdx.x; i < cnt; i += 256) { s += p1[i]; c += p2[i]; }
    sh1[threadIdx.x] = s; sh2[threadIdx.x] = c;
    __syncthreads();
    for (int o = 128; o > 0; o >>= 1) {
        if (threadIdx.x < o) { sh1[threadIdx.x] += sh1[threadIdx.x + o]; sh2[threadIdx.x] += sh2[threadIdx.x + o]; }
        __syncthreads();
    }
    if (threadIdx.x == 0)
        scal[1] = (sh2[0] > 0.f) ? (sh1[0] / sh2[0]) : scal[2];
}

// pack conv weights as duplicated bf16 pairs, K-padded (pad -> 0)
__global__ void tern_pack_kernel(const float* __restrict__ w, int CO, int K, int Kpad,
                                 const float* __restrict__ scal, uint32_t* __restrict__ out) {
    int idx = blockIdx.x * 256 + threadIdx.x;
    if (idx >= CO * Kpad) return;
    int co = idx / Kpad;
    int kg = idx - co * Kpad;
    float s = 0.f;
    if (kg < K) {
        float v = w[co * K + kg];
        float d = scal[0];
        s = (v > d) ? 1.f : ((v < -d) ? -1.f : 0.f);
    }
    uint32_t u = (uint32_t)__bfloat16_as_ushort(__float2bfloat16_rn(s));
    out[idx] = u * 0x00010001u;
}

// pack layer-1 input into [32][4][16384] (channel 3 zero-padded)
__global__ void pack_x_kernel(const float* __restrict__ x, uint32_t* __restrict__ out) {
    int idx = blockIdx.x * 256 + threadIdx.x;     // 32*4*16384 = 2097152
    int p = idx & 16383;
    int c = (idx >> 14) & 3;
    int n = idx >> 16;
    float v = 0.f;
    if (c < 3) v = x[((n * 3 + c) << 14) | p];
    out[idx] = pack_split(v);
}

// ----------------- implicit-GEMM conv (split-bf16, mma m16n8k16) ------------
#define GMT 64
#define GNT 128
#define SA_LD 36
#define SB_LD 136
#define SA_BUF (GMT * SA_LD)
#define SB_BUF (32 * SB_LD)
#define RED_OFF (2 * SA_BUF + 2 * SB_BUF)   // reduction scratch: 64*4*2 floats

__device__ __forceinline__ void mma_bf16(float& c0, float& c1, float& c2, float& c3,
                                         uint32_t a0, uint32_t a1, uint32_t a2, uint32_t a3,
                                         uint32_t b0, uint32_t b1) {
    asm volatile(
        "mma.sync.aligned.m16n8k16.row.col.f32.bf16.bf16.f32 "
        "{%0,%1,%2,%3}, {%4,%5,%6,%7}, {%8,%9}, {%0,%1,%2,%3};"
        : "+f"(c0), "+f"(c1), "+f"(c2), "+f"(c3)
        : "r"(a0), "r"(a1), "r"(a2), "r"(a3), "r"(b0), "r"(b1));
}

__global__ void __launch_bounds__(256) gemm_conv_kernel(
    const uint32_t* __restrict__ A, const uint32_t* __restrict__ Xp, float* __restrict__ C,
    int CI, int nk, int lw, int lhw, int N, int nbx,
    float* __restrict__ bnp1, float* __restrict__ bnp2) {
    extern __shared__ uint32_t smem_u[];
    uint32_t* sA = smem_u;
    uint32_t* sB = smem_u + 2 * SA_BUF;
    float* sRed = (float*)(smem_u + RED_OFF);    // [64][4] sum, then [64][4] sumsq

    const int tid = threadIdx.x;
    const int warp = tid >> 5, lane = tid & 31;
    const int wm = warp >> 2, wn = warp & 3;
    const int g = lane >> 2, tg = lane & 3;
    const int m0 = blockIdx.y * GMT;
    const int n0 = blockIdx.x * GNT;
    const int Kpad = nk * 32;

    // fixed pixel per thread (B gather)
    const int col = tid & 127;
    const int khalf = tid >> 7;
    const int W = 1 << lw;
    const int H = 1 << (lhw - lw);
    const int p = n0 + col;
    const int hp = (p >> lw) & (H - 1);
    const int wp = p & (W - 1);
    const uint32_t* xb = Xp + (((long)(p >> lhw) * CI) << lhw);

    // hoisted tap validity/offsets
    bool vh[3], vw[3];
    int ho[3], wo[3];
#pragma unroll
    for (int r = 0; r < 3; r++) {
        int hh = hp + r - 1;
        vh[r] = (unsigned)hh < (unsigned)H;
        ho[r] = hh << lw;
        int ww = wp + r - 1;
        vw[r] = (unsigned)ww < (unsigned)W;
        wo[r] = ww;
    }

    float acc[2][4][4];
#pragma unroll
    for (int mi = 0; mi < 2; mi++)
#pragma unroll
        for (int ni = 0; ni < 4; ni++)
#pragma unroll
            for (int q = 0; q < 4; q++) acc[mi][ni][q] = 0.f;

    uint4 rA[2];
    uint32_t rbw[16];

    auto gload = [&](int kc) {
#pragma unroll
        for (int i = 0; i < 2; i++) {
            int q = tid + i * 256;
            int r = q >> 3, c4 = q & 7;
            rA[i] = *(const uint4*)&A[(long)(m0 + r) * Kpad + kc * 32 + c4 * 4];
        }
        int base = kc * 32 + khalf;
        int ci = base / 9;
        int rs = base - ci * 9;
        int rr = rs / 3;
        int ss = rs - rr * 3;
#pragma unroll
        for (int i = 0; i < 16; i++) {
            uint32_t v = 0;
            if (vh[rr] && vw[ss])
                v = xb[(ci << lhw) + ho[rr] + wo[ss]];
            rbw[i] = v;
            ss += 2;
            if (ss >= 3) { ss -= 3; rr++; }
            if (rr >= 3) { rr -= 3; ci++; }
        }
    };
    auto sstore = [&](int buf) {
        uint32_t* dA = sA + buf * SA_BUF;
        uint32_t* dB = sB + buf * SB_BUF;
#pragma unroll
        for (int i = 0; i < 2; i++) {
            int q = tid + i * 256;
            int r = q >> 3, c4 = q & 7;
            *(uint4*)&dA[r * SA_LD + c4 * 4] = rA[i];
        }
#pragma unroll
        for (int i = 0; i < 16; i++)
            dB[(khalf + 2 * i) * SB_LD + col] = rbw[i];
    };

    gload(0);
    sstore(0);
    __syncthreads();

    for (int kc = 0; kc < nk; kc++) {
        const int buf = kc & 1;
        if (kc + 1 < nk) gload(kc + 1);

        const uint32_t* cA = sA + buf * SA_BUF;
        const uint32_t* cB = sB + buf * SB_BUF;
#pragma unroll
        for (int ks = 0; ks < 4; ks++) {
            uint32_t af[2][4], bf[4][2];
#pragma unroll
            for (int mi = 0; mi < 2; mi++) {
                const uint32_t* pa = cA + (wm * 32 + mi * 16 + g) * SA_LD + ks * 8 + tg;
                af[mi][0] = pa[0];
                af[mi][1] = pa[8 * SA_LD];
                af[mi][2] = pa[4];
                af[mi][3] = pa[8 * SA_LD + 4];
            }
#pragma unroll
            for (int ni = 0; ni < 4; ni++) {
                const uint32_t* pb = cB + (ks * 8 + tg) * SB_LD + wn * 32 + ni * 8 + g;
                bf[ni][0] = pb[0];
                bf[ni][1] = pb[4 * SB_LD];
            }
#pragma unroll
            for (int mi = 0; mi < 2; mi++)
#pragma unroll
                for (int ni = 0; ni < 4; ni++)
                    mma_bf16(acc[mi][ni][0], acc[mi][ni][1], acc[mi][ni][2], acc[mi][ni][3],
                             af[mi][0], af[mi][1], af[mi][2], af[mi][3],
                             bf[ni][0], bf[ni][1]);
        }
        if (kc + 1 < nk) sstore(buf ^ 1);
        __syncthreads();
    }

    // -------- epilogue: C store + fused BN partial stats --------
#pragma unroll
    for (int mi = 0; mi < 2; mi++) {
        const int row = m0 + wm * 32 + mi * 16 + g;
#pragma unroll
        for (int ni = 0; ni < 4; ni++) {
            const int colc = n0 + wn * 32 + ni * 8 + 2 * tg;
            float* p0 = &C[(long)row * N + colc];
            p0[0] = acc[mi][ni][0];
            p0[1] = acc[mi][ni][1];
            float* p1 = &C[(long)(row + 8) * N + colc];
            p1[0] = acc[mi][ni][2];
            p1[1] = acc[mi][ni][3];
        }
    }

#pragma unroll
    for (int mi = 0; mi < 2; mi++) {
        float a0 = 0.f, q0 = 0.f, a1 = 0.f, q1 = 0.f;
#pragma unroll
        for (int ni = 0; ni < 4; ni++) {
            a0 += acc[mi][ni][0] + acc[mi][ni][1];
            q0 += acc[mi][ni][0] * acc[mi][ni][0] + acc[mi][ni][1] * acc[mi][ni][1];
            a1 += acc[mi][ni][2] + acc[mi][ni][3];
            q1 += acc[mi][ni][2] * acc[mi][ni][2] + acc[mi][ni][3] * acc[mi][ni][3];
        }
#pragma unroll
        for (int off = 1; off <= 2; off <<= 1) {
            a0 += __shfl_xor_sync(0xffffffffu, a0, off);
            q0 += __shfl_xor_sync(0xffffffffu, q0, off);
            a1 += __shfl_xor_sync(0xffffffffu, a1, off);
            q1 += __shfl_xor_sync(0xffffffffu, q1, off);
        }
        if (tg == 0) {
            int r0 = wm * 32 + mi * 16 + g;
            sRed[r0 * 4 + wn] = a0;
            sRed[256 + r0 * 4 + wn] = q0;
            sRed[(r0 + 8) * 4 + wn] = a1;
            sRed[256 + (r0 + 8) * 4 + wn] = q1;
        }
    }
    __syncthreads();
    if (tid < 64) {
        float s = sRed[tid * 4] + sRed[tid * 4 + 1] + sRed[tid * 4 + 2] + sRed[tid * 4 + 3];
        float q = sRed[256 + tid * 4] + sRed[256 + tid * 4 + 1] + sRed[256 + tid * 4 + 2] + sRed[256 + tid * 4 + 3];
        bnp1[(long)(m0 + tid) * nbx + blockIdx.x] = s;
        bnp2[(long)(m0 + tid) * nbx + blockIdx.x] = q;
    }
}

// ------------------------------ batchnorm ----------------------------------
__global__ void bn_final_kernel(const float* __restrict__ p1, const float* __restrict__ p2,
                                int nbx, float invM,
                                const float* __restrict__ gamma, const float* __restrict__ beta,
                                float* __restrict__ scale, float* __restrict__ shift) {
    __shared__ float sh1[256], sh2[256];
    const int c = blockIdx.x;
    float s = 0.f, q = 0.f;
    for (int i = threadIdx.x; i < nbx; i += 256) {
        s += p1[(long)c * nbx + i];
        q += p2[(long)c * nbx + i];
    }
    sh1[threadIdx.x] = s; sh2[threadIdx.x] = q; __syncthreads();
    for (int o = 128; o > 0; o >>= 1) {
        if (threadIdx.x < o) { sh1[threadIdx.x] += sh1[threadIdx.x + o]; sh2[threadIdx.x] += sh2[threadIdx.x + o]; }
        __syncthreads();
    }
    if (threadIdx.x == 0) {
        float mean = sh1[0] * invM;
        float var = sh2[0] * invM - mean * mean;
        float istd = rsqrtf(var + 1e-5f);
        float sc = gamma[c] * istd;
        scale[c] = sc;
        shift[c] = beta[c] - mean * sc;
    }
}

// read C-major conv buffer, write pooled NCHW PACKED (hi,lo) uint32
__global__ void bn_relu_pool_cm_kernel(const float* __restrict__ y, const float* __restrict__ scale,
                                       const float* __restrict__ shift, uint32_t* __restrict__ out,
                                       int C, int H, int W, long total) {
    long idx = (long)blockIdx.x * 256 + threadIdx.x;
    if (idx >= total) return;
    const int W2 = W >> 1, H2 = H >> 1;
    int wo = (int)(idx % W2);
    long t = idx / W2;
    int ho = (int)(t % H2); t /= H2;
    int c = (int)(t % C);
    int n = (int)(t / C);
    const float* yp = y + (((long)c * N_BATCH + n) * H + 2 * ho) * W + 2 * wo;
    float sc = scale[c], sh = shift[c];
    float a = fmaxf(sc * yp[0] + sh, sc * yp[1] + sh);
    float b = fmaxf(sc * yp[W] + sh, sc * yp[W + 1] + sh);
    out[idx] = pack_split(fmaxf(fmaxf(a, b), 0.f));
}

// --------------------------------- FC --------------------------------------
// FC1 split-K; inline ternarize + fused masked stats; packed activations.
__global__ void fc1_partial_kernel(const uint32_t* __restrict__ x, const float* __restrict__ w,
                                   const float* __restrict__ scal, float* __restrict__ part,
                                   float* __restrict__ sp1, float* __restrict__ sp2) {
    __shared__ float s_w[64][33];
    __shared__ __align__(16) float s_x[32][34];
    __shared__ float r1[256], r2[256];
    const int K = 32768;
    const int o0 = blockIdx.x * 64;
    const int k0 = blockIdx.y * 2048;
    const int tid = threadIdx.x;
    const int tx = tid & 15;
    const int ty = tid >> 4;
    const float d = scal[0];

    float acc[4][2];
#pragma unroll
    for (int i = 0; i < 4; i++) { acc[i][0] = 0.f; acc[i][1] = 0.f; }
    float ms = 0.f, mc = 0.f;

    for (int kk = k0; kk < k0 + 2048; kk += 32) {
#pragma unroll
        for (int t = 0; t < 8; t++) {
            int idx = tid + t * 256;
            int row = idx >> 5, colw = idx & 31;
            float v = w[(long)(o0 + row) * K + kk + colw];
            float av = fabsf(v);
            if (av > d) { ms += av; mc += 1.f; }
            s_w[row][colw] = (v > d) ? 1.f : ((v < -d) ? -1.f : 0.f);
        }
#pragma unroll
        for (int t = 0; t < 4; t++) {
            int idx = tid + t * 256;
            int b = idx >> 5, colw = idx & 31;
            s_x[colw][b] = unpack_split(x[(long)b * K + kk + colw]);
        }
        __syncthreads();
#pragma unroll
        for (int j = 0; j < 32; j++) {
            float2 xv = *(const float2*)&s_x[j][tx * 2];
#pragma unroll
            for (int i = 0; i < 4; i++) {
                float wv = s_w[ty * 4 + i][j];
                acc[i][0] += wv * xv.x;
                acc[i][1] += wv * xv.y;
            }
        }
        __syncthreads();
    }
#pragma unroll
    for (int i = 0; i < 4; i++)
#pragma unroll
        for (int q = 0; q < 2; q++)
            part[((long)blockIdx.y * 32 + tx * 2 + q) * 1024 + o0 + ty * 4 + i] = acc[i][q];

    // masked-stat block reduction -> deterministic slot
    r1[tid] = ms; r2[tid] = mc; __syncthreads();
    for (int o = 128; o > 0; o >>= 1) {
        if (tid < o) { r1[tid] += r1[tid + o]; r2[tid] += r2[tid + o]; }
        __syncthreads();
    }
    if (tid == 0) {
        int slot = blockIdx.y * 16 + blockIdx.x;
        sp1[slot] = r1[0];
        sp2[slot] = r2[0];
    }
}

__global__ void fc1_post_kernel(const float* __restrict__ part, const float* __restrict__ bias,
                                const float* __restrict__ scal, float* __restrict__ out) {
    int idx = blockIdx.x * 256 + threadIdx.x;
    if (idx >= 32 * 1024) return;
    int o = idx & 1023;
    float s = 0.f;
#pragma unroll
    for (int ks = 0; ks < 16; ks++) s += part[(long)ks * 32 * 1024 + idx];
    out[idx] = fmaxf(s * scal[1] + bias[o], 0.f);
}

__global__ void fc2_kernel(const float* __restrict__ x, const float* __restrict__ w,
                           const float* __restrict__ bias, const float* __restrict__ scal,
                           float* __restrict__ out) {
    int gw = (blockIdx.x * 256 + threadIdx.x) >> 5;
    int lane = threadIdx.x & 31;
    if (gw >= 32 * 1000) return;
    int b = gw / 1000, o = gw % 1000;
    const float d = scal[0];
    float a = 0.f;
    for (int k = lane; k < 1024; k += 32) {
        float wv = w[o * 1024 + k];
        float sg = (wv > d) ? 1.f : ((wv < -d) ? -1.f : 0.f);
        a += x[b * 1024 + k] * sg;
    }
#pragma unroll
    for (int off = 16; off; off >>= 1) a += __shfl_down_sync(0xffffffffu, a, off);
    if (lane == 0) out[b * 1000 + o] = a * scal[1] + bias[o];
}

// ------------------------------- host side ---------------------------------
static float* scal_slot(int slot) {
    float* sc;
    cudaGetSymbolAddress((void**)&sc, g_scal);
    return sc + 4 * slot;
}

static int stats_nb(long n) {
    long nb = (n + 4095) / 4096;
    if (nb > 512) nb = 512;
    if (nb < 1) nb = 1;
    return (int)nb;
}

static void tern_stats_delta(const float* w, long n, int slot) {
    float* p1;
    cudaGetSymbolAddress((void**)&p1, g_part1);
    int nb = stats_nb(n);
    abs_sum_kernel<<<nb, 256>>>(w, n, p1);
    delta_final_kernel<<<1, 256>>>(p1, nb, 1.0f / (float)n, scal_slot(slot));
}

static void tern_stats_full(const float* w, long n, int slot) {
    float *p1, *p2;
    cudaGetSymbolAddress((void**)&p1, g_part1);
    cudaGetSymbolAddress((void**)&p2, g_part2);
    tern_stats_delta(w, n, slot);
    int nb = stats_nb(n);
    masked_sum_kernel<<<nb, 256>>>(w, n, scal_slot(slot), p1, p2);
    alpha_final_kernel<<<1, 256>>>(p1, p2, nb, scal_slot(slot));
}

static void tern_pack(const float* w, int CO, int K, int Kpad, int slot, uint32_t* out) {
    tern_stats_delta(w, (long)CO * K, slot);
    tern_pack_kernel<<<(CO * Kpad + 255) / 256, 256>>>(w, CO, K, Kpad, scal_slot(slot), out);
}

static void conv_layer(const uint32_t* xin, const uint32_t* Apack, const float* gamma, const float* beta,
                       float* conv_buf, uint32_t* pool_buf, int CI, int CO, int K, int lw, int lhw) {
    float *bp1, *bp2, *bsc, *bsh;
    cudaGetSymbolAddress((void**)&bp1, g_bnp1);
    cudaGetSymbolAddress((void**)&bp2, g_bnp2);
    cudaGetSymbolAddress((void**)&bsc, g_bnscale);
    cudaGetSymbolAddress((void**)&bsh, g_bnshift);

    const int N = N_BATCH << lhw;
    const int nk = (K + 31) / 32;
    const int nbx = N / GNT;
    size_t smem = (size_t)(RED_OFF + 512) * 4;
    cudaFuncSetAttribute(gemm_conv_kernel, cudaFuncAttributeMaxDynamicSharedMemorySize, (int)smem);
    gemm_conv_kernel<<<dim3(nbx, CO / GMT), 256, smem>>>(Apack, xin, conv_buf,
                                                         CI, nk, lw, lhw, N, nbx, bp1, bp2);
    const int H = 1 << (lhw - lw), W = 1 << lw;
    bn_final_kernel<<<CO, 256>>>(bp1, bp2, nbx, 1.0f / (float)N, gamma, beta, bsc, bsh);
    long total = (long)N_BATCH * CO * (H / 2) * (W / 2);
    bn_relu_pool_cm_kernel<<<(int)((total + 255) / 256), 256>>>(conv_buf, bsc, bsh, pool_buf,
                                                                CO, H, W, total);
}

extern "C" void kernel_launch(void* const* d_in, const int* in_sizes, int n_in,
                              void* d_out, int out_size) {
    const float* x   = (const float*)d_in[0];
    const float* w1  = (const float*)d_in[1];
    const float* g1  = (const float*)d_in[3];
    const float* be1 = (const float*)d_in[4];
    const float* w2  = (const float*)d_in[5];
    const float* g2  = (const float*)d_in[7];
    const float* be2 = (const float*)d_in[8];
    const float* w3  = (const float*)d_in[9];
    const float* g3  = (const float*)d_in[11];
    const float* be3 = (const float*)d_in[12];
    const float* w4  = (const float*)d_in[13];
    const float* g4  = (const float*)d_in[15];
    const float* be4 = (const float*)d_in[16];
    const float* fw1 = (const float*)d_in[17];
    const float* fb1 = (const float*)d_in[18];
    const float* fw2 = (const float*)d_in[19];
    const float* fb2 = (const float*)d_in[20];
    float* out = (float*)d_out;

    float *p_conv, *p_fc1, *p_fc1part, *p_sp1, *p_sp2;
    uint32_t *p_pool, *p_xpack, *pA1, *pA2, *pA3, *pA4;
    cudaGetSymbolAddress((void**)&p_conv, g_conv);
    cudaGetSymbolAddress((void**)&p_pool, g_pool);
    cudaGetSymbolAddress((void**)&p_xpack, g_xpack);
    cudaGetSymbolAddress((void**)&pA1, g_A1);
    cudaGetSymbolAddress((void**)&pA2, g_A2);
    cudaGetSymbolAddress((void**)&pA3, g_A3);
    cudaGetSymbolAddress((void**)&pA4, g_A4);
    cudaGetSymbolAddress((void**)&p_fc1, g_fc1);
    cudaGetSymbolAddress((void**)&p_fc1part, g_fc1part);
    cudaGetSymbolAddress((void**)&p_sp1, g_part1);
    cudaGetSymbolAddress((void**)&p_sp2, g_part2);

    // 1) ternarize conv weights -> packed dup-bf16 sign buffers
    tern_pack(w1, 64, 27, 32, 0, pA1);
    tern_pack(w2, 128, 576, 576, 1, pA2);
    tern_pack(w3, 256, 1152, 1152, 2, pA3);
    tern_pack(w4, 512, 2304, 2304, 3, pA4);
    // FC deltas (alpha for fw1 comes fused from fc1; fw2 full stats)
    tern_stats_delta(fw1, (long)in_sizes[17], 4);
    tern_stats_full(fw2, (long)in_sizes[19], 5);

    // 2) pack layer-1 input (with zero pad channel)
    pack_x_kernel<<<2097152 / 256, 256>>>(x, p_xpack);

    // 3) conv blocks: implicit-GEMM (+ fused BN stats) + BN-final + relu-pool(pack)
    conv_layer(p_xpack, pA1, g1, be1, p_conv, p_pool, 4,   64,  32,   7, 14);
    conv_layer(p_pool,  pA2, g2, be2, p_conv, p_pool, 64,  128, 576,  6, 12);
    conv_layer(p_pool,  pA3, g3, be3, p_conv, p_pool, 128, 256, 1152, 5, 10);
    conv_layer(p_pool,  pA4, g4, be4, p_conv, p_pool, 256, 512, 2304, 4, 8);

    // 4) FC1 (split-K, inline ternarize + fused alpha stats) + alpha + relu
    fc1_partial_kernel<<<dim3(16, 16), 256>>>(p_pool, fw1, scal_slot(4), p_fc1part, p_sp1, p_sp2);
    alpha_final_kernel<<<1, 256>>>(p_sp1, p_sp2, 256, scal_slot(4));
    fc1_post_kernel<<<(32 * 1024 + 255) / 256, 256>>>(p_fc1part, fb1, scal_slot(4), p_fc1);

    // 5) FC2 -> output
    fc2_kernel<<<(32 * 1000 * 32 + 255) / 256, 256>>>(p_fc1, fw2, fb2, scal_slot(5), out);
}

// round 7
// speedup vs baseline: 1.4225x; 1.4225x over previous
#include <cuda_runtime.h>
#include <cuda_bf16.h>
#include <cstdint>

// ---------------------------------------------------------------------------
// TernaryCNN v5:
//  - implicit-GEMM convs, split-bf16 (hi/lo) packed activations, sign weights
//  - gather producer: pure scalar arithmetic (NO register-array indexing ->
//    no local-memory spills; this was the R6 regression)
//  - BN batch stats fused into GEMM epilogue; pool writes packed activations
//  - FC1 ternary stats fused into FC1; conv weight stats batched (3 launches)
// ---------------------------------------------------------------------------

#define N_BATCH 32

// -------------------- device scratch (static, no allocs) -------------------
__device__ float g_conv[33554432];        // conv out C-major [co][n][h][w]
__device__ uint32_t g_pool[8388608];      // pooled NCHW, packed (hi,lo)
__device__ uint32_t g_xpack[2097152];     // packed layer-1 input [32][4][16384]
__device__ uint32_t g_A1[2048];           // packed tern weights 64 x 32
__device__ uint32_t g_A2[73728];          // 128 x 576
__device__ uint32_t g_A3[294912];         // 256 x 1152
__device__ uint32_t g_A4[1179648];        // 512 x 2304
__device__ float g_fc1[32 * 1024];
__device__ float g_fc1part[16 * 32 * 1024];
__device__ float g_part1[512];
__device__ float g_part2[512];
__device__ float g_cpart[4 * 128];        // batched conv-weight abs partials
__device__ float g_scal[32];              // 8 slots x 4: [0]=delta [1]=alpha [2]=mean
__device__ float g_bnp1[262144];
__device__ float g_bnp2[262144];
__device__ float g_bnscale[512];
__device__ float g_bnshift[512];

// ----------------------------- helpers -------------------------------------
__device__ __forceinline__ uint32_t pack_split(float x) {
    __nv_bfloat16 h = __float2bfloat16_rn(x);
    float hf = __bfloat162float(h);
    __nv_bfloat16 l = __float2bfloat16_rn(x - hf);
    return ((uint32_t)__bfloat16_as_ushort(l) << 16) | (uint32_t)__bfloat16_as_ushort(h);
}
__device__ __forceinline__ float unpack_split(uint32_t u) {
    __nv_bfloat16 h = __ushort_as_bfloat16((unsigned short)(u & 0xffff));
    __nv_bfloat16 l = __ushort_as_bfloat16((unsigned short)(u >> 16));
    return __bfloat162float(h) + __bfloat162float(l);
}

// ------------------- batched conv-weight ternarize ---------------------------
// sizes: w1 64*27, w2 128*576, w3 256*1152, w4 512*2304
#define CW_NB 128
__constant__ long c_cwn[4] = {1728, 73728, 294912, 1179648};

__global__ void cw_abs_sum_kernel(const float* __restrict__ w1, const float* __restrict__ w2,
                                  const float* __restrict__ w3, const float* __restrict__ w4,
                                  float* __restrict__ part) {
    __shared__ float sh[256];
    const int t = blockIdx.y;
    const float* w = (t == 0) ? w1 : (t == 1) ? w2 : (t == 2) ? w3 : w4;
    const long n = c_cwn[t];
    float a = 0.f;
    for (long i = (long)blockIdx.x * 256 + threadIdx.x; i < n; i += (long)CW_NB * 256)
        a += fabsf(w[i]);
    sh[threadIdx.x] = a; __syncthreads();
    for (int o = 128; o > 0; o >>= 1) {
        if (threadIdx.x < o) sh[threadIdx.x] += sh[threadIdx.x + o];
        __syncthreads();
    }
    if (threadIdx.x == 0) part[t * CW_NB + blockIdx.x] = sh[0];
}

__global__ void cw_delta_final_kernel(const float* __restrict__ part, float* __restrict__ scal) {
    __shared__ float sh[128];
    const int t = blockIdx.x;
    sh[threadIdx.x] = part[t * CW_NB + threadIdx.x];
    __syncthreads();
    for (int o = 64; o > 0; o >>= 1) {
        if (threadIdx.x < o) sh[threadIdx.x] += sh[threadIdx.x + o];
        __syncthreads();
    }
    if (threadIdx.x == 0) {
        float mean = sh[0] / (float)c_cwn[t];
        scal[4 * t] = 0.7f * mean;
        scal[4 * t + 2] = mean;
    }
}

// pack all 4 conv weight tensors: grid-stride over concatenated padded extents
__global__ void cw_pack_kernel(const float* __restrict__ w1, const float* __restrict__ w2,
                               const float* __restrict__ w3, const float* __restrict__ w4,
                               const float* __restrict__ scal,
                               uint32_t* __restrict__ o1, uint32_t* __restrict__ o2,
                               uint32_t* __restrict__ o3, uint32_t* __restrict__ o4) {
    // padded sizes: 64*32=2048, 73728, 294912, 1179648 ; total 1550336
    const int total = 2048 + 73728 + 294912 + 1179648;
    for (int idx = blockIdx.x * 256 + threadIdx.x; idx < total; idx += gridDim.x * 256) {
        const float* w; uint32_t* o; float d; int K, Kpad; int j = idx;
        if (j < 2048) { w = w1; o = o1; d = scal[0]; K = 27; Kpad = 32; }
        else if ((j -= 2048) < 73728) { w = w2; o = o2; d = scal[4]; K = 576; Kpad = 576; }
        else if ((j -= 73728) < 294912) { w = w3; o = o3; d = scal[8]; K = 1152; Kpad = 1152; }
        else { j -= 294912; w = w4; o = o4; d = scal[12]; K = 2304; Kpad = 2304; }
        int co = j / Kpad;
        int kg = j - co * Kpad;
        float s = 0.f;
        if (kg < K) {
            float v = w[co * K + kg];
            s = (v > d) ? 1.f : ((v < -d) ? -1.f : 0.f);
        }
        uint32_t u = (uint32_t)__bfloat16_as_ushort(__float2bfloat16_rn(s));
        o[j] = u * 0x00010001u;
    }
}

// ----------------------------- fc2 stats ------------------------------------
__global__ void abs_sum_kernel(const float* __restrict__ w, long n, float* __restrict__ part) {
    __shared__ float sh[256];
    float a = 0.f;
    const long stride = (long)gridDim.x * 256;
    for (long i = (long)blockIdx.x * 256 + threadIdx.x; i < n; i += stride)
        a += fabsf(w[i]);
    sh[threadIdx.x] = a; __syncthreads();
    for (int o = 128; o > 0; o >>= 1) {
        if (threadIdx.x < o) sh[threadIdx.x] += sh[threadIdx.x + o];
        __syncthreads();
    }
    if (threadIdx.x == 0) part[blockIdx.x] = sh[0];
}

__global__ void delta_final_kernel(const float* __restrict__ part, int nb, float inv_n,
                                   float* __restrict__ scal) {
    __shared__ float sh[256];
    float a = 0.f;
    for (int i = threadIdx.x; i < nb; i += 256) a += part[i];
    sh[threadIdx.x] = a; __syncthreads();
    for (int o = 128; o > 0; o >>= 1) {
        if (threadIdx.x < o) sh[threadIdx.x] += sh[threadIdx.x + o];
        __syncthreads();
    }
    if (threadIdx.x == 0) {
        float mean = sh[0] * inv_n;
        scal[0] = 0.7f * mean;
        scal[2] = mean;
    }
}

__global__ void masked_sum_kernel(const float* __restrict__ w, long n, const float* __restrict__ scal,
                                  float* __restrict__ p1, float* __restrict__ p2) {
    __shared__ float sh1[256], sh2[256];
    const float delta = scal[0];
    const long stride = (long)gridDim.x * 256;
    float s = 0.f, c = 0.f;
    for (long i = (long)blockIdx.x * 256 + threadIdx.x; i < n; i += stride) {
        float v = fabsf(w[i]);
        if (v > delta) { s += v; c += 1.f; }
    }
    sh1[threadIdx.x] = s; sh2[threadIdx.x] = c; __syncthreads();
    for (int o = 128; o > 0; o >>= 1) {
        if (threadIdx.x < o) { sh1[threadIdx.x] += sh1[threadIdx.x + o]; sh2[threadIdx.x] += sh2[threadIdx.x + o]; }
        __syncthreads();
    }
    if (threadIdx.x == 0) { p1[blockIdx.x] = sh1[0]; p2[blockIdx.x] = sh2[0]; }
}

__global__ void alpha_final_kernel(const float* __restrict__ p1, const float* __restrict__ p2,
                                   int cnt, float* __restrict__ scal) {
    __shared__ float sh1[256], sh2[256];
    float s = 0.f, c = 0.f;
    for (int i = threadIdx.x; i < cnt; i += 256) { s += p1[i]; c += p2[i]; }
    sh1[threadIdx.x] = s; sh2[threadIdx.x] = c;
    __syncthreads();
    for (int o = 128; o > 0; o >>= 1) {
        if (threadIdx.x < o) { sh1[threadIdx.x] += sh1[threadIdx.x + o]; sh2[threadIdx.x] += sh2[threadIdx.x + o]; }
        __syncthreads();
    }
    if (threadIdx.x == 0)
        scal[1] = (sh2[0] > 0.f) ? (sh1[0] / sh2[0]) : scal[2];
}

// pack layer-1 input into [32][4][16384] (channel 3 zero-padded)
__global__ void pack_x_kernel(const float* __restrict__ x, uint32_t* __restrict__ out) {
    int idx = blockIdx.x * 256 + threadIdx.x;
    int p = idx & 16383;
    int c = (idx >> 14) & 3;
    int n = idx >> 16;
    float v = 0.f;
    if (c < 3) v = x[((n * 3 + c) << 14) | p];
    out[idx] = pack_split(v);
}

// ----------------- implicit-GEMM conv (split-bf16, mma m16n8k16) ------------
#define GMT 64
#define GNT 128
#define SA_LD 36
#define SB_LD 136
#define SA_BUF (GMT * SA_LD)
#define SB_BUF (32 * SB_LD)
#define RED_OFF (2 * SA_BUF + 2 * SB_BUF)

__device__ __forceinline__ void mma_bf16(float& c0, float& c1, float& c2, float& c3,
                                         uint32_t a0, uint32_t a1, uint32_t a2, uint32_t a3,
                                         uint32_t b0, uint32_t b1) {
    asm volatile(
        "mma.sync.aligned.m16n8k16.row.col.f32.bf16.bf16.f32 "
        "{%0,%1,%2,%3}, {%4,%5,%6,%7}, {%8,%9}, {%0,%1,%2,%3};"
        : "+f"(c0), "+f"(c1), "+f"(c2), "+f"(c3)
        : "r"(a0), "r"(a1), "r"(a2), "r"(a3), "r"(b0), "r"(b1));
}

__global__ void __launch_bounds__(256) gemm_conv_kernel(
    const uint32_t* __restrict__ A, const uint32_t* __restrict__ Xp, float* __restrict__ C,
    int CI, int nk, int lw, int lhw, int N, int nbx,
    float* __restrict__ bnp1, float* __restrict__ bnp2) {
    extern __shared__ uint32_t smem_u[];
    uint32_t* sA = smem_u;
    uint32_t* sB = smem_u + 2 * SA_BUF;
    float* sRed = (float*)(smem_u + RED_OFF);

    const int tid = threadIdx.x;
    const int warp = tid >> 5, lane = tid & 31;
    const int wm = warp >> 2, wn = warp & 3;
    const int g = lane >> 2, tg = lane & 3;
    const int m0 = blockIdx.y * GMT;
    const int n0 = blockIdx.x * GNT;
    const int Kpad = nk * 32;

    // fixed pixel per thread (B gather); all scalar state, no arrays
    const int col = tid & 127;
    const int khalf = tid >> 7;
    const int W = 1 << lw;
    const int H = 1 << (lhw - lw);
    const int p = n0 + col;
    const int hp = (p >> lw) & (H - 1);
    const int wp = p & (W - 1);
    const uint32_t* xb = Xp + (((long)(p >> lhw) * CI) << lhw);

    // 3-bit validity masks, tested with dynamic shifts (register ops only)
    const int hmask = ((hp - 1 >= 0) ? 1 : 0) | 2 | ((hp + 1 < H) ? 4 : 0);
    const int wmask = ((wp - 1 >= 0) ? 1 : 0) | 2 | ((wp + 1 < W) ? 4 : 0);
    const int boff0 = ((hp - 1) << lw) + (wp - 1);   // offset at rr=0,ss=0, ci=0

    float acc[2][4][4];
#pragma unroll
    for (int mi = 0; mi < 2; mi++)
#pragma unroll
        for (int ni = 0; ni < 4; ni++)
#pragma unroll
            for (int q = 0; q < 4; q++) acc[mi][ni][q] = 0.f;

    uint4 rA[2];
    uint32_t rbw[16];

    auto gload = [&](int kc) {
#pragma unroll
        for (int i = 0; i < 2; i++) {
            int q = tid + i * 256;
            int r = q >> 3, c4 = q & 7;
            rA[i] = *(const uint4*)&A[(long)(m0 + r) * Kpad + kc * 32 + c4 * 4];
        }
        int base = kc * 32 + khalf;
        int ci = base / 9;
        int rs = base - ci * 9;
        int rr = rs / 3;
        int ss = rs - rr * 3;
        int cioff = ci << lhw;
#pragma unroll
        for (int i = 0; i < 16; i++) {
            uint32_t v = 0;
            if (((hmask >> rr) & (wmask >> ss) & 1) != 0)
                v = xb[cioff + boff0 + (rr << lw) + ss];
            rbw[i] = v;
            ss += 2;
            if (ss >= 3) { ss -= 3; rr++; }
            if (rr >= 3) { rr -= 3; cioff += 1 << lhw; }
        }
    };
    auto sstore = [&](int buf) {
        uint32_t* dA = sA + buf * SA_BUF;
        uint32_t* dB = sB + buf * SB_BUF;
#pragma unroll
        for (int i = 0; i < 2; i++) {
            int q = tid + i * 256;
            int r = q >> 3, c4 = q & 7;
            *(uint4*)&dA[r * SA_LD + c4 * 4] = rA[i];
        }
#pragma unroll
        for (int i = 0; i < 16; i++)
            dB[(khalf + 2 * i) * SB_LD + col] = rbw[i];
    };

    gload(0);
    sstore(0);
    __syncthreads();

    for (int kc = 0; kc < nk; kc++) {
        const int buf = kc & 1;
        if (kc + 1 < nk) gload(kc + 1);

        const uint32_t* cA = sA + buf * SA_BUF;
        const uint32_t* cB = sB + buf * SB_BUF;
#pragma unroll
        for (int ks = 0; ks < 4; ks++) {
            uint32_t af[2][4], bf[4][2];
#pragma unroll
            for (int mi = 0; mi < 2; mi++) {
                const uint32_t* pa = cA + (wm * 32 + mi * 16 + g) * SA_LD + ks * 8 + tg;
                af[mi][0] = pa[0];
                af[mi][1] = pa[8 * SA_LD];
                af[mi][2] = pa[4];
                af[mi][3] = pa[8 * SA_LD + 4];
            }
#pragma unroll
            for (int ni = 0; ni < 4; ni++) {
                const uint32_t* pb = cB + (ks * 8 + tg) * SB_LD + wn * 32 + ni * 8 + g;
                bf[ni][0] = pb[0];
                bf[ni][1] = pb[4 * SB_LD];
            }
#pragma unroll
            for (int mi = 0; mi < 2; mi++)
#pragma unroll
                for (int ni = 0; ni < 4; ni++)
                    mma_bf16(acc[mi][ni][0], acc[mi][ni][1], acc[mi][ni][2], acc[mi][ni][3],
                             af[mi][0], af[mi][1], af[mi][2], af[mi][3],
                             bf[ni][0], bf[ni][1]);
        }
        if (kc + 1 < nk) sstore(buf ^ 1);
        __syncthreads();
    }

    // -------- epilogue: C store + fused BN partial stats --------
#pragma unroll
    for (int mi = 0; mi < 2; mi++) {
        const int row = m0 + wm * 32 + mi * 16 + g;
#pragma unroll
        for (int ni = 0; ni < 4; ni++) {
            const int colc = n0 + wn * 32 + ni * 8 + 2 * tg;
            float* p0 = &C[(long)row * N + colc];
            p0[0] = acc[mi][ni][0];
            p0[1] = acc[mi][ni][1];
            float* p1 = &C[(long)(row + 8) * N + colc];
            p1[0] = acc[mi][ni][2];
            p1[1] = acc[mi][ni][3];
        }
    }

#pragma unroll
    for (int mi = 0; mi < 2; mi++) {
        float a0 = 0.f, q0 = 0.f, a1 = 0.f, q1 = 0.f;
#pragma unroll
        for (int ni = 0; ni < 4; ni++) {
            a0 += acc[mi][ni][0] + acc[mi][ni][1];
            q0 += acc[mi][ni][0] * acc[mi][ni][0] + acc[mi][ni][1] * acc[mi][ni][1];
            a1 += acc[mi][ni][2] + acc[mi][ni][3];
            q1 += acc[mi][ni][2] * acc[mi][ni][2] + acc[mi][ni][3] * acc[mi][ni][3];
        }
#pragma unroll
        for (int off = 1; off <= 2; off <<= 1) {
            a0 += __shfl_xor_sync(0xffffffffu, a0, off);
            q0 += __shfl_xor_sync(0xffffffffu, q0, off);
            a1 += __shfl_xor_sync(0xffffffffu, a1, off);
            q1 += __shfl_xor_sync(0xffffffffu, q1, off);
        }
        if (tg == 0) {
            int r0 = wm * 32 + mi * 16 + g;
            sRed[r0 * 4 + wn] = a0;
            sRed[256 + r0 * 4 + wn] = q0;
            sRed[(r0 + 8) * 4 + wn] = a1;
            sRed[256 + (r0 + 8) * 4 + wn] = q1;
        }
    }
    __syncthreads();
    if (tid < 64) {
        float s = sRed[tid * 4] + sRed[tid * 4 + 1] + sRed[tid * 4 + 2] + sRed[tid * 4 + 3];
        float q = sRed[256 + tid * 4] + sRed[256 + tid * 4 + 1] + sRed[256 + tid * 4 + 2] + sRed[256 + tid * 4 + 3];
        bnp1[(long)(m0 + tid) * nbx + blockIdx.x] = s;
        bnp2[(long)(m0 + tid) * nbx + blockIdx.x] = q;
    }
}

// ------------------------------ batchnorm ----------------------------------
__global__ void bn_final_kernel(const float* __restrict__ p1, const float* __restrict__ p2,
                                int nbx, float invM,
                                const float* __restrict__ gamma, const float* __restrict__ beta,
                                float* __restrict__ scale, float* __restrict__ shift) {
    __shared__ float sh1[256], sh2[256];
    const int c = blockIdx.x;
    float s = 0.f, q = 0.f;
    for (int i = threadIdx.x; i < nbx; i += 256) {
        s += p1[(long)c * nbx + i];
        q += p2[(long)c * nbx + i];
    }
    sh1[threadIdx.x] = s; sh2[threadIdx.x] = q; __syncthreads();
    for (int o = 128; o > 0; o >>= 1) {
        if (threadIdx.x < o) { sh1[threadIdx.x] += sh1[threadIdx.x + o]; sh2[threadIdx.x] += sh2[threadIdx.x + o]; }
        __syncthreads();
    }
    if (threadIdx.x == 0) {
        float mean = sh1[0] * invM;
        float var = sh2[0] * invM - mean * mean;
        float istd = rsqrtf(var + 1e-5f);
        float sc = gamma[c] * istd;
        scale[c] = sc;
        shift[c] = beta[c] - mean * sc;
    }
}

__global__ void bn_relu_pool_cm_kernel(const float* __restrict__ y, const float* __restrict__ scale,
                                       const float* __restrict__ shift, uint32_t* __restrict__ out,
                                       int C, int H, int W, long total) {
    long idx = (long)blockIdx.x * 256 + threadIdx.x;
    if (idx >= total) return;
    const int W2 = W >> 1, H2 = H >> 1;
    int wo = (int)(idx % W2);
    long t = idx / W2;
    int ho = (int)(t % H2); t /= H2;
    int c = (int)(t % C);
    int n = (int)(t / C);
    const float* yp = y + (((long)c * N_BATCH + n) * H + 2 * ho) * W + 2 * wo;
    float sc = scale[c], sh = shift[c];
    float a = fmaxf(sc * yp[0] + sh, sc * yp[1] + sh);
    float b = fmaxf(sc * yp[W] + sh, sc * yp[W + 1] + sh);
    out[idx] = pack_split(fmaxf(fmaxf(a, b), 0.f));
}

// --------------------------------- FC --------------------------------------
__global__ void fc1_partial_kernel(const uint32_t* __restrict__ x, const float* __restrict__ w,
                                   const float* __restrict__ scal, float* __restrict__ part,
                                   float* __restrict__ sp1, float* __restrict__ sp2) {
    __shared__ float s_w[64][33];
    __shared__ __align__(16) float s_x[32][34];
    __shared__ float r1[256], r2[256];
    const int K = 32768;
    const int o0 = blockIdx.x * 64;
    const int k0 = blockIdx.y * 2048;
    const int tid = threadIdx.x;
    const int tx = tid & 15;
    const int ty = tid >> 4;
    const float d = scal[0];

    float acc[4][2];
#pragma unroll
    for (int i = 0; i < 4; i++) { acc[i][0] = 0.f; acc[i][1] = 0.f; }
    float ms = 0.f, mc = 0.f;

    for (int kk = k0; kk < k0 + 2048; kk += 32) {
#pragma unroll
        for (int t = 0; t < 8; t++) {
            int idx = tid + t * 256;
            int row = idx >> 5, colw = idx & 31;
            float v = w[(long)(o0 + row) * K + kk + colw];
            float av = fabsf(v);
            if (av > d) { ms += av; mc += 1.f; }
            s_w[row][colw] = (v > d) ? 1.f : ((v < -d) ? -1.f : 0.f);
        }
#pragma unroll
        for (int t = 0; t < 4; t++) {
            int idx = tid + t * 256;
            int b = idx >> 5, colw = idx & 31;
            s_x[colw][b] = unpack_split(x[(long)b * K + kk + colw]);
        }
        __syncthreads();
#pragma unroll
        for (int j = 0; j < 32; j++) {
            float2 xv = *(const float2*)&s_x[j][tx * 2];
#pragma unroll
            for (int i = 0; i < 4; i++) {
                float wv = s_w[ty * 4 + i][j];
                acc[i][0] += wv * xv.x;
                acc[i][1] += wv * xv.y;
            }
        }
        __syncthreads();
    }
#pragma unroll
    for (int i = 0; i < 4; i++)
#pragma unroll
        for (int q = 0; q < 2; q++)
            part[((long)blockIdx.y * 32 + tx * 2 + q) * 1024 + o0 + ty * 4 + i] = acc[i][q];

    r1[tid] = ms; r2[tid] = mc; __syncthreads();
    for (int o = 128; o > 0; o >>= 1) {
        if (tid < o) { r1[tid] += r1[tid + o]; r2[tid] += r2[tid + o]; }
        __syncthreads();
    }
    if (tid == 0) {
        int slot = blockIdx.y * 16 + blockIdx.x;
        sp1[slot] = r1[0];
        sp2[slot] = r2[0];
    }
}

__global__ void fc1_post_kernel(const float* __restrict__ part, const float* __restrict__ bias,
                                const float* __restrict__ scal, float* __restrict__ out) {
    int idx = blockIdx.x * 256 + threadIdx.x;
    if (idx >= 32 * 1024) return;
    int o = idx & 1023;
    float s = 0.f;
#pragma unroll
    for (int ks = 0; ks < 16; ks++) s += part[(long)ks * 32 * 1024 + idx];
    out[idx] = fmaxf(s * scal[1] + bias[o], 0.f);
}

__global__ void fc2_kernel(const float* __restrict__ x, const float* __restrict__ w,
                           const float* __restrict__ bias, const float* __restrict__ scal,
                           float* __restrict__ out) {
    int gw = (blockIdx.x * 256 + threadIdx.x) >> 5;
    int lane = threadIdx.x & 31;
    if (gw >= 32 * 1000) return;
    int b = gw / 1000, o = gw % 1000;
    const float d = scal[0];
    float a = 0.f;
    for (int k = lane; k < 1024; k += 32) {
        float wv = w[o * 1024 + k];
        float sg = (wv > d) ? 1.f : ((wv < -d) ? -1.f : 0.f);
        a += x[b * 1024 + k] * sg;
    }
#pragma unroll
    for (int off = 16; off; off >>= 1) a += __shfl_down_sync(0xffffffffu, a, off);
    if (lane == 0) out[b * 1000 + o] = a * scal[1] + bias[o];
}

// ------------------------------- host side ---------------------------------
static float* scal_slot(int slot) {
    float* sc;
    cudaGetSymbolAddress((void**)&sc, g_scal);
    return sc + 4 * slot;
}

static int stats_nb(long n) {
    long nb = (n + 4095) / 4096;
    if (nb > 512) nb = 512;
    if (nb < 1) nb = 1;
    return (int)nb;
}

static void conv_layer(const uint32_t* xin, const uint32_t* Apack, const float* gamma, const float* beta,
                       float* conv_buf, uint32_t* pool_buf, int CI, int CO, int K, int lw, int lhw) {
    float *bp1, *bp2, *bsc, *bsh;
    cudaGetSymbolAddress((void**)&bp1, g_bnp1);
    cudaGetSymbolAddress((void**)&bp2, g_bnp2);
    cudaGetSymbolAddress((void**)&bsc, g_bnscale);
    cudaGetSymbolAddress((void**)&bsh, g_bnshift);

    const int N = N_BATCH << lhw;
    const int nk = (K + 31) / 32;
    const int nbx = N / GNT;
    size_t smem = (size_t)(RED_OFF + 512) * 4;
    cudaFuncSetAttribute(gemm_conv_kernel, cudaFuncAttributeMaxDynamicSharedMemorySize, (int)smem);
    gemm_conv_kernel<<<dim3(nbx, CO / GMT), 256, smem>>>(Apack, xin, conv_buf,
                                                         CI, nk, lw, lhw, N, nbx, bp1, bp2);
    const int H = 1 << (lhw - lw), W = 1 << lw;
    bn_final_kernel<<<CO, 256>>>(bp1, bp2, nbx, 1.0f / (float)N, gamma, beta, bsc, bsh);
    long total = (long)N_BATCH * CO * (H / 2) * (W / 2);
    bn_relu_pool_cm_kernel<<<(int)((total + 255) / 256), 256>>>(conv_buf, bsc, bsh, pool_buf,
                                                                CO, H, W, total);
}

extern "C" void kernel_launch(void* const* d_in, const int* in_sizes, int n_in,
                              void* d_out, int out_size) {
    const float* x   = (const float*)d_in[0];
    const float* w1  = (const float*)d_in[1];
    const float* g1  = (const float*)d_in[3];
    const float* be1 = (const float*)d_in[4];
    const float* w2  = (const float*)d_in[5];
    const float* g2  = (const float*)d_in[7];
    const float* be2 = (const float*)d_in[8];
    const float* w3  = (const float*)d_in[9];
    const float* g3  = (const float*)d_in[11];
    const float* be3 = (const float*)d_in[12];
    const float* w4  = (const float*)d_in[13];
    const float* g4  = (const float*)d_in[15];
    const float* be4 = (const float*)d_in[16];
    const float* fw1 = (const float*)d_in[17];
    const float* fb1 = (const float*)d_in[18];
    const float* fw2 = (const float*)d_in[19];
    const float* fb2 = (const float*)d_in[20];
    float* out = (float*)d_out;

    float *p_conv, *p_fc1, *p_fc1part, *p_sp1, *p_sp2, *p_cpart, *p_scal;
    uint32_t *p_pool, *p_xpack, *pA1, *pA2, *pA3, *pA4;
    cudaGetSymbolAddress((void**)&p_conv, g_conv);
    cudaGetSymbolAddress((void**)&p_pool, g_pool);
    cudaGetSymbolAddress((void**)&p_xpack, g_xpack);
    cudaGetSymbolAddress((void**)&pA1, g_A1);
    cudaGetSymbolAddress((void**)&pA2, g_A2);
    cudaGetSymbolAddress((void**)&pA3, g_A3);
    cudaGetSymbolAddress((void**)&pA4, g_A4);
    cudaGetSymbolAddress((void**)&p_fc1, g_fc1);
    cudaGetSymbolAddress((void**)&p_fc1part, g_fc1part);
    cudaGetSymbolAddress((void**)&p_sp1, g_part1);
    cudaGetSymbolAddress((void**)&p_sp2, g_part2);
    cudaGetSymbolAddress((void**)&p_cpart, g_cpart);
    cudaGetSymbolAddress((void**)&p_scal, g_scal);

    // 1) conv-weight ternarize, batched: 3 launches total
    cw_abs_sum_kernel<<<dim3(CW_NB, 4), 256>>>(w1, w2, w3, w4, p_cpart);
    cw_delta_final_kernel<<<4, 128>>>(p_cpart, p_scal);
    cw_pack_kernel<<<1024, 256>>>(w1, w2, w3, w4, p_scal, pA1, pA2, pA3, pA4);

    // 2) FC deltas (fw1 alpha fused into fc1; fw2 full stats)
    {
        long n1 = (long)in_sizes[17];
        int nb1 = stats_nb(n1);
        abs_sum_kernel<<<nb1, 256>>>(fw1, n1, p_sp1);
        delta_final_kernel<<<1, 256>>>(p_sp1, nb1, 1.0f / (float)n1, scal_slot(4));
        long n2 = (long)in_sizes[19];
        int nb2 = stats_nb(n2);
        abs_sum_kernel<<<nb2, 256>>>(fw2, n2, p_sp1);
        delta_final_kernel<<<1, 256>>>(p_sp1, nb2, 1.0f / (float)n2, scal_slot(5));
        masked_sum_kernel<<<nb2, 256>>>(fw2, n2, scal_slot(5), p_sp1, p_sp2);
        alpha_final_kernel<<<1, 256>>>(p_sp1, p_sp2, nb2, scal_slot(5));
    }

    // 3) pack layer-1 input
    pack_x_kernel<<<2097152 / 256, 256>>>(x, p_xpack);

    // 4) conv blocks
    conv_layer(p_xpack, pA1, g1, be1, p_conv, p_pool, 4,   64,  32,   7, 14);
    conv_layer(p_pool,  pA2, g2, be2, p_conv, p_pool, 64,  128, 576,  6, 12);
    conv_layer(p_pool,  pA3, g3, be3, p_conv, p_pool, 128, 256, 1152, 5, 10);
    conv_layer(p_pool,  pA4, g4, be4, p_conv, p_pool, 256, 512, 2304, 4, 8);

    // 5) FC1 (split-K, inline ternarize + fused alpha stats) + alpha + relu
    fc1_partial_kernel<<<dim3(16, 16), 256>>>(p_pool, fw1, scal_slot(4), p_fc1part, p_sp1, p_sp2);
    alpha_final_kernel<<<1, 256>>>(p_sp1, p_sp2, 256, scal_slot(4));
    fc1_post_kernel<<<(32 * 1024 + 255) / 256, 256>>>(p_fc1part, fb1, scal_slot(4), p_fc1);

    // 6) FC2 -> output
    fc2_kernel<<<(32 * 1000 * 32 + 255) / 256, 256>>>(p_fc1, fw2, fb2, scal_slot(5), out);
}

// round 10
// speedup vs baseline: 1.7247x; 1.2124x over previous
#include <cuda_runtime.h>
#include <cuda_bf16.h>
#include <cstdint>

// ---------------------------------------------------------------------------
// TernaryCNN v6 (re-bench; prior attempt hit infra failure, not kernel error):
//  - implicit-GEMM convs, split-bf16 packed activations, sign weights
//  - block tile 128x128 (templated; 64x128 for layer1) -> halved B gather
//  - BN stats fused in GEMM epilogue; pool emits packed activations
//  - FC1 stats fused; conv weight stats batched; float4 abs_sum
// ---------------------------------------------------------------------------

#define N_BATCH 32

// -------------------- device scratch (static, no allocs) -------------------
__device__ float g_conv[33554432];        // conv out C-major [co][n][h][w]
__device__ uint32_t g_pool[8388608];      // pooled NCHW, packed (hi,lo)
__device__ uint32_t g_xpack[2097152];     // packed layer-1 input [32][4][16384]
__device__ uint32_t g_A1[2048];
__device__ uint32_t g_A2[73728];
__device__ uint32_t g_A3[294912];
__device__ uint32_t g_A4[1179648];
__device__ float g_fc1[32 * 1024];
__device__ float g_fc1part[16 * 32 * 1024];
__device__ float g_part1[512];
__device__ float g_part2[512];
__device__ float g_cpart[4 * 128];
__device__ float g_scal[32];              // 8 slots x 4
__device__ float g_bnp1[262144];
__device__ float g_bnp2[262144];
__device__ float g_bnscale[512];
__device__ float g_bnshift[512];

// ----------------------------- helpers -------------------------------------
__device__ __forceinline__ uint32_t pack_split(float x) {
    __nv_bfloat16 h = __float2bfloat16_rn(x);
    float hf = __bfloat162float(h);
    __nv_bfloat16 l = __float2bfloat16_rn(x - hf);
    return ((uint32_t)__bfloat16_as_ushort(l) << 16) | (uint32_t)__bfloat16_as_ushort(h);
}
__device__ __forceinline__ float unpack_split(uint32_t u) {
    __nv_bfloat16 h = __ushort_as_bfloat16((unsigned short)(u & 0xffff));
    __nv_bfloat16 l = __ushort_as_bfloat16((unsigned short)(u >> 16));
    return __bfloat162float(h) + __bfloat162float(l);
}

// ------------------- batched conv-weight ternarize --------------------------
#define CW_NB 128
__constant__ long c_cwn[4] = {1728, 73728, 294912, 1179648};

__global__ void cw_abs_sum_kernel(const float* __restrict__ w1, const float* __restrict__ w2,
                                  const float* __restrict__ w3, const float* __restrict__ w4,
                                  float* __restrict__ part) {
    __shared__ float sh[256];
    const int t = blockIdx.y;
    const float* w = (t == 0) ? w1 : (t == 1) ? w2 : (t == 2) ? w3 : w4;
    const long n = c_cwn[t];
    float a = 0.f;
    for (long i = (long)blockIdx.x * 256 + threadIdx.x; i < n; i += (long)CW_NB * 256)
        a += fabsf(w[i]);
    sh[threadIdx.x] = a; __syncthreads();
    for (int o = 128; o > 0; o >>= 1) {
        if (threadIdx.x < o) sh[threadIdx.x] += sh[threadIdx.x + o];
        __syncthreads();
    }
    if (threadIdx.x == 0) part[t * CW_NB + blockIdx.x] = sh[0];
}

__global__ void cw_delta_final_kernel(const float* __restrict__ part, float* __restrict__ scal) {
    __shared__ float sh[128];
    const int t = blockIdx.x;
    sh[threadIdx.x] = part[t * CW_NB + threadIdx.x];
    __syncthreads();
    for (int o = 64; o > 0; o >>= 1) {
        if (threadIdx.x < o) sh[threadIdx.x] += sh[threadIdx.x + o];
        __syncthreads();
    }
    if (threadIdx.x == 0) {
        float mean = sh[0] / (float)c_cwn[t];
        scal[4 * t] = 0.7f * mean;
        scal[4 * t + 2] = mean;
    }
}

__global__ void cw_pack_kernel(const float* __restrict__ w1, const float* __restrict__ w2,
                               const float* __restrict__ w3, const float* __restrict__ w4,
                               const float* __restrict__ scal,
                               uint32_t* __restrict__ o1, uint32_t* __restrict__ o2,
                               uint32_t* __restrict__ o3, uint32_t* __restrict__ o4) {
    const int total = 2048 + 73728 + 294912 + 1179648;
    for (int idx = blockIdx.x * 256 + threadIdx.x; idx < total; idx += gridDim.x * 256) {
        const float* w; uint32_t* o; float d; int K, Kpad; int j = idx;
        if (j < 2048) { w = w1; o = o1; d = scal[0]; K = 27; Kpad = 32; }
        else if ((j -= 2048) < 73728) { w = w2; o = o2; d = scal[4]; K = 576; Kpad = 576; }
        else if ((j -= 73728) < 294912) { w = w3; o = o3; d = scal[8]; K = 1152; Kpad = 1152; }
        else { j -= 294912; w = w4; o = o4; d = scal[12]; K = 2304; Kpad = 2304; }
        int co = j / Kpad;
        int kg = j - co * Kpad;
        float s = 0.f;
        if (kg < K) {
            float v = w[co * K + kg];
            s = (v > d) ? 1.f : ((v < -d) ? -1.f : 0.f);
        }
        uint32_t u = (uint32_t)__bfloat16_as_ushort(__float2bfloat16_rn(s));
        o[j] = u * 0x00010001u;
    }
}

// ----------------------------- fc stats (float4) ----------------------------
__global__ void abs_sum4_kernel(const float4* __restrict__ w, long n4, float* __restrict__ part) {
    __shared__ float sh[256];
    float a = 0.f;
    const long stride = (long)gridDim.x * 256;
    for (long i = (long)blockIdx.x * 256 + threadIdx.x; i < n4; i += stride) {
        float4 v = w[i];
        a += fabsf(v.x) + fabsf(v.y) + fabsf(v.z) + fabsf(v.w);
    }
    sh[threadIdx.x] = a; __syncthreads();
    for (int o = 128; o > 0; o >>= 1) {
        if (threadIdx.x < o) sh[threadIdx.x] += sh[threadIdx.x + o];
        __syncthreads();
    }
    if (threadIdx.x == 0) part[blockIdx.x] = sh[0];
}

__global__ void delta_final_kernel(const float* __restrict__ part, int nb, float inv_n,
                                   float* __restrict__ scal) {
    __shared__ float sh[256];
    float a = 0.f;
    for (int i = threadIdx.x; i < nb; i += 256) a += part[i];
    sh[threadIdx.x] = a; __syncthreads();
    for (int o = 128; o > 0; o >>= 1) {
        if (threadIdx.x < o) sh[threadIdx.x] += sh[threadIdx.x + o];
        __syncthreads();
    }
    if (threadIdx.x == 0) {
        float mean = sh[0] * inv_n;
        scal[0] = 0.7f * mean;
        scal[2] = mean;
    }
}

__global__ void masked_sum4_kernel(const float4* __restrict__ w, long n4, const float* __restrict__ scal,
                                   float* __restrict__ p1, float* __restrict__ p2) {
    __shared__ float sh1[256], sh2[256];
    const float delta = scal[0];
    const long stride = (long)gridDim.x * 256;
    float s = 0.f, c = 0.f;
    for (long i = (long)blockIdx.x * 256 + threadIdx.x; i < n4; i += stride) {
        float4 v = w[i];
        float a0 = fabsf(v.x), a1 = fabsf(v.y), a2 = fabsf(v.z), a3 = fabsf(v.w);
        if (a0 > delta) { s += a0; c += 1.f; }
        if (a1 > delta) { s += a1; c += 1.f; }
        if (a2 > delta) { s += a2; c += 1.f; }
        if (a3 > delta) { s += a3; c += 1.f; }
    }
    sh1[threadIdx.x] = s; sh2[threadIdx.x] = c; __syncthreads();
    for (int o = 128; o > 0; o >>= 1) {
        if (threadIdx.x < o) { sh1[threadIdx.x] += sh1[threadIdx.x + o]; sh2[threadIdx.x] += sh2[threadIdx.x + o]; }
        __syncthreads();
    }
    if (threadIdx.x == 0) { p1[blockIdx.x] = sh1[0]; p2[blockIdx.x] = sh2[0]; }
}

__global__ void alpha_final_kernel(const float* __restrict__ p1, const float* __restrict__ p2,
                                   int cnt, float* __restrict__ scal) {
    __shared__ float sh1[256], sh2[256];
    float s = 0.f, c = 0.f;
    for (int i = threadIdx.x; i < cnt; i += 256) { s += p1[i]; c += p2[i]; }
    sh1[threadIdx.x] = s; sh2[threadIdx.x] = c;
    __syncthreads();
    for (int o = 128; o > 0; o >>= 1) {
        if (threadIdx.x < o) { sh1[threadIdx.x] += sh1[threadIdx.x + o]; sh2[threadIdx.x] += sh2[threadIdx.x + o]; }
        __syncthreads();
    }
    if (threadIdx.x == 0)
        scal[1] = (sh2[0] > 0.f) ? (sh1[0] / sh2[0]) : scal[2];
}

__global__ void pack_x_kernel(const float* __restrict__ x, uint32_t* __restrict__ out) {
    int idx = blockIdx.x * 256 + threadIdx.x;
    int p = idx & 16383;
    int c = (idx >> 14) & 3;
    int n = idx >> 16;
    float v = 0.f;
    if (c < 3) v = x[((n * 3 + c) << 14) | p];
    out[idx] = pack_split(v);
}

// ----------------- implicit-GEMM conv (split-bf16, mma m16n8k16) ------------
// Templated on MI (16-row mma tiles per warp): MB = MI*32 rows per block.
#define GNT 128
#define SA_LD 36
#define SB_LD 136
#define SB_BUF (32 * SB_LD)

__device__ __forceinline__ void mma_bf16(float& c0, float& c1, float& c2, float& c3,
                                         uint32_t a0, uint32_t a1, uint32_t a2, uint32_t a3,
                                         uint32_t b0, uint32_t b1) {
    asm volatile(
        "mma.sync.aligned.m16n8k16.row.col.f32.bf16.bf16.f32 "
        "{%0,%1,%2,%3}, {%4,%5,%6,%7}, {%8,%9}, {%0,%1,%2,%3};"
        : "+f"(c0), "+f"(c1), "+f"(c2), "+f"(c3)
        : "r"(a0), "r"(a1), "r"(a2), "r"(a3), "r"(b0), "r"(b1));
}

template <int MI>
__global__ void __launch_bounds__(256) gemm_conv_kernel(
    const uint32_t* __restrict__ A, const uint32_t* __restrict__ Xp, float* __restrict__ C,
    int CI, int nk, int lw, int lhw, int N, int nbx,
    float* __restrict__ bnp1, float* __restrict__ bnp2) {
    constexpr int MB = MI * 32;
    constexpr int SA_BUF = MB * SA_LD;
    extern __shared__ uint32_t smem_u[];
    uint32_t* sA = smem_u;
    uint32_t* sB = smem_u + 2 * SA_BUF;
    float* sRed = (float*)(smem_u + 2 * SA_BUF + 2 * SB_BUF);   // [MB][4] x2

    const int tid = threadIdx.x;
    const int warp = tid >> 5, lane = tid & 31;
    const int wm = warp >> 2, wn = warp & 3;     // wm 0..1, wn 0..3
    const int g = lane >> 2, tg = lane & 3;
    const int m0 = blockIdx.y * MB;
    const int n0 = blockIdx.x * GNT;
    const int Kpad = nk * 32;

    // fixed pixel per thread (B gather)
    const int col = tid & 127;
    const int khalf = tid >> 7;
    const int W = 1 << lw;
    const int H = 1 << (lhw - lw);
    const int p = n0 + col;
    const int hp = (p >> lw) & (H - 1);
    const int wp = p & (W - 1);
    const uint32_t* xb = Xp + (((long)(p >> lhw) * CI) << lhw);

    const int hmask = ((hp - 1 >= 0) ? 1 : 0) | 2 | ((hp + 1 < H) ? 4 : 0);
    const int wmask = ((wp - 1 >= 0) ? 1 : 0) | 2 | ((wp + 1 < W) ? 4 : 0);
    const int boff0 = ((hp - 1) << lw) + (wp - 1);

    float acc[MI][4][4];
#pragma unroll
    for (int mi = 0; mi < MI; mi++)
#pragma unroll
        for (int ni = 0; ni < 4; ni++)
#pragma unroll
            for (int q = 0; q < 4; q++) acc[mi][ni][q] = 0.f;

    uint4 rA[MI];
    uint32_t rbw[16];

    auto gload = [&](int kc) {
#pragma unroll
        for (int i = 0; i < MI; i++) {
            int q = tid + i * 256;
            int r = q >> 3, c4 = q & 7;
            rA[i] = *(const uint4*)&A[(long)(m0 + r) * Kpad + kc * 32 + c4 * 4];
        }
        int base = kc * 32 + khalf;
        int ci = base / 9;
        int rs = base - ci * 9;
        int rr = rs / 3;
        int ss = rs - rr * 3;
        int cioff = ci << lhw;
#pragma unroll
        for (int i = 0; i < 16; i++) {
            uint32_t v = 0;
            if (((hmask >> rr) & (wmask >> ss) & 1) != 0)
                v = xb[cioff + boff0 + (rr << lw) + ss];
            rbw[i] = v;
            ss += 2;
            if (ss >= 3) { ss -= 3; rr++; }
            if (rr >= 3) { rr -= 3; cioff += 1 << lhw; }
        }
    };
    auto sstore = [&](int buf) {
        uint32_t* dA = sA + buf * SA_BUF;
        uint32_t* dB = sB + buf * SB_BUF;
#pragma unroll
        for (int i = 0; i < MI; i++) {
            int q = tid + i * 256;
            int r = q >> 3, c4 = q & 7;
            *(uint4*)&dA[r * SA_LD + c4 * 4] = rA[i];
        }
#pragma unroll
        for (int i = 0; i < 16; i++)
            dB[(khalf + 2 * i) * SB_LD + col] = rbw[i];
    };

    gload(0);
    sstore(0);
    __syncthreads();

    for (int kc = 0; kc < nk; kc++) {
        const int buf = kc & 1;
        if (kc + 1 < nk) gload(kc + 1);

        const uint32_t* cA = sA + buf * SA_BUF;
        const uint32_t* cB = sB + buf * SB_BUF;
#pragma unroll
        for (int ks = 0; ks < 4; ks++) {
            uint32_t af[MI][4], bf[4][2];
#pragma unroll
            for (int mi = 0; mi < MI; mi++) {
                const uint32_t* pa = cA + (wm * (MI * 16) + mi * 16 + g) * SA_LD + ks * 8 + tg;
                af[mi][0] = pa[0];
                af[mi][1] = pa[8 * SA_LD];
                af[mi][2] = pa[4];
                af[mi][3] = pa[8 * SA_LD + 4];
            }
#pragma unroll
            for (int ni = 0; ni < 4; ni++) {
                const uint32_t* pb = cB + (ks * 8 + tg) * SB_LD + wn * 32 + ni * 8 + g;
                bf[ni][0] = pb[0];
                bf[ni][1] = pb[4 * SB_LD];
            }
#pragma unroll
            for (int mi = 0; mi < MI; mi++)
#pragma unroll
                for (int ni = 0; ni < 4; ni++)
                    mma_bf16(acc[mi][ni][0], acc[mi][ni][1], acc[mi][ni][2], acc[mi][ni][3],
                             af[mi][0], af[mi][1], af[mi][2], af[mi][3],
                             bf[ni][0], bf[ni][1]);
        }
        if (kc + 1 < nk) sstore(buf ^ 1);
        __syncthreads();
    }

    // -------- epilogue: C store + fused BN partial stats --------
#pragma unroll
    for (int mi = 0; mi < MI; mi++) {
        const int row = m0 + wm * (MI * 16) + mi * 16 + g;
#pragma unroll
        for (int ni = 0; ni < 4; ni++) {
            const int colc = n0 + wn * 32 + ni * 8 + 2 * tg;
            float* p0 = &C[(long)row * N + colc];
            p0[0] = acc[mi][ni][0];
            p0[1] = acc[mi][ni][1];
            float* p1 = &C[(long)(row + 8) * N + colc];
            p1[0] = acc[mi][ni][2];
            p1[1] = acc[mi][ni][3];
        }
    }

#pragma unroll
    for (int mi = 0; mi < MI; mi++) {
        float a0 = 0.f, q0 = 0.f, a1 = 0.f, q1 = 0.f;
#pragma unroll
        for (int ni = 0; ni < 4; ni++) {
            a0 += acc[mi][ni][0] + acc[mi][ni][1];
            q0 += acc[mi][ni][0] * acc[mi][ni][0] + acc[mi][ni][1] * acc[mi][ni][1];
            a1 += acc[mi][ni][2] + acc[mi][ni][3];
            q1 += acc[mi][ni][2] * acc[mi][ni][2] + acc[mi][ni][3] * acc[mi][ni][3];
        }
#pragma unroll
        for (int off = 1; off <= 2; off <<= 1) {
            a0 += __shfl_xor_sync(0xffffffffu, a0, off);
            q0 += __shfl_xor_sync(0xffffffffu, q0, off);
            a1 += __shfl_xor_sync(0xffffffffu, a1, off);
            q1 += __shfl_xor_sync(0xffffffffu, q1, off);
        }
        if (tg == 0) {
            int r0 = wm * (MI * 16) + mi * 16 + g;
            sRed[r0 * 4 + wn] = a0;
            sRed[MB * 4 + r0 * 4 + wn] = q0;
            sRed[(r0 + 8) * 4 + wn] = a1;
            sRed[MB * 4 + (r0 + 8) * 4 + wn] = q1;
        }
    }
    __syncthreads();
    if (tid < MB) {
        float s = sRed[tid * 4] + sRed[tid * 4 + 1] + sRed[tid * 4 + 2] + sRed[tid * 4 + 3];
        float q = sRed[MB * 4 + tid * 4] + sRed[MB * 4 + tid * 4 + 1]
                + sRed[MB * 4 + tid * 4 + 2] + sRed[MB * 4 + tid * 4 + 3];
        bnp1[(long)(m0 + tid) * nbx + blockIdx.x] = s;
        bnp2[(long)(m0 + tid) * nbx + blockIdx.x] = q;
    }
}

// ------------------------------ batchnorm ----------------------------------
__global__ void bn_final_kernel(const float* __restrict__ p1, const float* __restrict__ p2,
                                int nbx, float invM,
                                const float* __restrict__ gamma, const float* __restrict__ beta,
                                float* __restrict__ scale, float* __restrict__ shift) {
    __shared__ float sh1[256], sh2[256];
    const int c = blockIdx.x;
    float s = 0.f, q = 0.f;
    for (int i = threadIdx.x; i < nbx; i += 256) {
        s += p1[(long)c * nbx + i];
        q += p2[(long)c * nbx + i];
    }
    sh1[threadIdx.x] = s; sh2[threadIdx.x] = q; __syncthreads();
    for (int o = 128; o > 0; o >>= 1) {
        if (threadIdx.x < o) { sh1[threadIdx.x] += sh1[threadIdx.x + o]; sh2[threadIdx.x] += sh2[threadIdx.x + o]; }
        __syncthreads();
    }
    if (threadIdx.x == 0) {
        float mean = sh1[0] * invM;
        float var = sh2[0] * invM - mean * mean;
        float istd = rsqrtf(var + 1e-5f);
        float sc = gamma[c] * istd;
        scale[c] = sc;
        shift[c] = beta[c] - mean * sc;
    }
}

__global__ void bn_relu_pool_cm_kernel(const float* __restrict__ y, const float* __restrict__ scale,
                                       const float* __restrict__ shift, uint32_t* __restrict__ out,
                                       int C, int H, int W, long total) {
    long idx = (long)blockIdx.x * 256 + threadIdx.x;
    if (idx >= total) return;
    const int W2 = W >> 1, H2 = H >> 1;
    int wo = (int)(idx % W2);
    long t = idx / W2;
    int ho = (int)(t % H2); t /= H2;
    int c = (int)(t % C);
    int n = (int)(t / C);
    const float* yp = y + (((long)c * N_BATCH + n) * H + 2 * ho) * W + 2 * wo;
    float sc = scale[c], sh = shift[c];
    float a = fmaxf(sc * yp[0] + sh, sc * yp[1] + sh);
    float b = fmaxf(sc * yp[W] + sh, sc * yp[W + 1] + sh);
    out[idx] = pack_split(fmaxf(fmaxf(a, b), 0.f));
}

// --------------------------------- FC --------------------------------------
__global__ void fc1_partial_kernel(const uint32_t* __restrict__ x, const float* __restrict__ w,
                                   const float* __restrict__ scal, float* __restrict__ part,
                                   float* __restrict__ sp1, float* __restrict__ sp2) {
    __shared__ float s_w[64][33];
    __shared__ __align__(16) float s_x[32][34];
    __shared__ float r1[256], r2[256];
    const int K = 32768;
    const int o0 = blockIdx.x * 64;
    const int k0 = blockIdx.y * 2048;
    const int tid = threadIdx.x;
    const int tx = tid & 15;
    const int ty = tid >> 4;
    const float d = scal[0];

    float acc[4][2];
#pragma unroll
    for (int i = 0; i < 4; i++) { acc[i][0] = 0.f; acc[i][1] = 0.f; }
    float ms = 0.f, mc = 0.f;

    for (int kk = k0; kk < k0 + 2048; kk += 32) {
#pragma unroll
        for (int t = 0; t < 8; t++) {
            int idx = tid + t * 256;
            int row = idx >> 5, colw = idx & 31;
            float v = w[(long)(o0 + row) * K + kk + colw];
            float av = fabsf(v);
            if (av > d) { ms += av; mc += 1.f; }
            s_w[row][colw] = (v > d) ? 1.f : ((v < -d) ? -1.f : 0.f);
        }
#pragma unroll
        for (int t = 0; t < 4; t++) {
            int idx = tid + t * 256;
            int b = idx >> 5, colw = idx & 31;
            s_x[colw][b] = unpack_split(x[(long)b * K + kk + colw]);
        }
        __syncthreads();
#pragma unroll
        for (int j = 0; j < 32; j++) {
            float2 xv = *(const float2*)&s_x[j][tx * 2];
#pragma unroll
            for (int i = 0; i < 4; i++) {
                float wv = s_w[ty * 4 + i][j];
                acc[i][0] += wv * xv.x;
                acc[i][1] += wv * xv.y;
            }
        }
        __syncthreads();
    }
#pragma unroll
    for (int i = 0; i < 4; i++)
#pragma unroll
        for (int q = 0; q < 2; q++)
            part[((long)blockIdx.y * 32 + tx * 2 + q) * 1024 + o0 + ty * 4 + i] = acc[i][q];

    r1[tid] = ms; r2[tid] = mc; __syncthreads();
    for (int o = 128; o > 0; o >>= 1) {
        if (tid < o) { r1[tid] += r1[tid + o]; r2[tid] += r2[tid + o]; }
        __syncthreads();
    }
    if (tid == 0) {
        int slot = blockIdx.y * 16 + blockIdx.x;
        sp1[slot] = r1[0];
        sp2[slot] = r2[0];
    }
}

__global__ void fc1_post_kernel(const float* __restrict__ part, const float* __restrict__ bias,
                                const float* __restrict__ scal, float* __restrict__ out) {
    int idx = blockIdx.x * 256 + threadIdx.x;
    if (idx >= 32 * 1024) return;
    int o = idx & 1023;
    float s = 0.f;
#pragma unroll
    for (int ks = 0; ks < 16; ks++) s += part[(long)ks * 32 * 1024 + idx];
    out[idx] = fmaxf(s * scal[1] + bias[o], 0.f);
}

__global__ void fc2_kernel(const float* __restrict__ x, const float* __restrict__ w,
                           const float* __restrict__ bias, const float* __restrict__ scal,
                           float* __restrict__ out) {
    int gw = (blockIdx.x * 256 + threadIdx.x) >> 5;
    int lane = threadIdx.x & 31;
    if (gw >= 32 * 1000) return;
    int b = gw / 1000, o = gw % 1000;
    const float d = scal[0];
    float a = 0.f;
    for (int k = lane; k < 1024; k += 32) {
        float wv = w[o * 1024 + k];
        float sg = (wv > d) ? 1.f : ((wv < -d) ? -1.f : 0.f);
        a += x[b * 1024 + k] * sg;
    }
#pragma unroll
    for (int off = 16; off; off >>= 1) a += __shfl_down_sync(0xffffffffu, a, off);
    if (lane == 0) out[b * 1000 + o] = a * scal[1] + bias[o];
}

// ------------------------------- host side ---------------------------------
static float* scal_slot(int slot) {
    float* sc;
    cudaGetSymbolAddress((void**)&sc, g_scal);
    return sc + 4 * slot;
}

static int stats_nb(long n) {
    long nb = (n + 4095) / 4096;
    if (nb > 512) nb = 512;
    if (nb < 1) nb = 1;
    return (int)nb;
}

static void conv_layer(const uint32_t* xin, const uint32_t* Apack, const float* gamma, const float* beta,
                       float* conv_buf, uint32_t* pool_buf, int CI, int CO, int K, int lw, int lhw) {
    float *bp1, *bp2, *bsc, *bsh;
    cudaGetSymbolAddress((void**)&bp1, g_bnp1);
    cudaGetSymbolAddress((void**)&bp2, g_bnp2);
    cudaGetSymbolAddress((void**)&bsc, g_bnscale);
    cudaGetSymbolAddress((void**)&bsh, g_bnshift);

    const int N = N_BATCH << lhw;
    const int nk = (K + 31) / 32;
    const int nbx = N / GNT;

    if (CO >= 128) {
        constexpr int MB = 128;
        size_t smem = (size_t)(2 * MB * SA_LD + 2 * SB_BUF + MB * 8) * 4;
        cudaFuncSetAttribute(gemm_conv_kernel<4>, cudaFuncAttributeMaxDynamicSharedMemorySize, (int)smem);
        gemm_conv_kernel<4><<<dim3(nbx, CO / MB), 256, smem>>>(Apack, xin, conv_buf,
                                                               CI, nk, lw, lhw, N, nbx, bp1, bp2);
    } else {
        constexpr int MB = 64;
        size_t smem = (size_t)(2 * MB * SA_LD + 2 * SB_BUF + MB * 8) * 4;
        cudaFuncSetAttribute(gemm_conv_kernel<2>, cudaFuncAttributeMaxDynamicSharedMemorySize, (int)smem);
        gemm_conv_kernel<2><<<dim3(nbx, CO / MB), 256, smem>>>(Apack, xin, conv_buf,
                                                               CI, nk, lw, lhw, N, nbx, bp1, bp2);
    }

    const int H = 1 << (lhw - lw), W = 1 << lw;
    bn_final_kernel<<<CO, 256>>>(bp1, bp2, nbx, 1.0f / (float)N, gamma, beta, bsc, bsh);
    long total = (long)N_BATCH * CO * (H / 2) * (W / 2);
    bn_relu_pool_cm_kernel<<<(int)((total + 255) / 256), 256>>>(conv_buf, bsc, bsh, pool_buf,
                                                                CO, H, W, total);
}

extern "C" void kernel_launch(void* const* d_in, const int* in_sizes, int n_in,
                              void* d_out, int out_size) {
    const float* x   = (const float*)d_in[0];
    const float* w1  = (const float*)d_in[1];
    const float* g1  = (const float*)d_in[3];
    const float* be1 = (const float*)d_in[4];
    const float* w2  = (const float*)d_in[5];
    const float* g2  = (const float*)d_in[7];
    const float* be2 = (const float*)d_in[8];
    const float* w3  = (const float*)d_in[9];
    const float* g3  = (const float*)d_in[11];
    const float* be3 = (const float*)d_in[12];
    const float* w4  = (const float*)d_in[13];
    const float* g4  = (const float*)d_in[15];
    const float* be4 = (const float*)d_in[16];
    const float* fw1 = (const float*)d_in[17];
    const float* fb1 = (const float*)d_in[18];
    const float* fw2 = (const float*)d_in[19];
    const float* fb2 = (const float*)d_in[20];
    float* out = (float*)d_out;

    float *p_conv, *p_fc1, *p_fc1part, *p_sp1, *p_sp2, *p_cpart, *p_scal;
    uint32_t *p_pool, *p_xpack, *pA1, *pA2, *pA3, *pA4;
    cudaGetSymbolAddress((void**)&p_conv, g_conv);
    cudaGetSymbolAddress((void**)&p_pool, g_pool);
    cudaGetSymbolAddress((void**)&p_xpack, g_xpack);
    cudaGetSymbolAddress((void**)&pA1, g_A1);
    cudaGetSymbolAddress((void**)&pA2, g_A2);
    cudaGetSymbolAddress((void**)&pA3, g_A3);
    cudaGetSymbolAddress((void**)&pA4, g_A4);
    cudaGetSymbolAddress((void**)&p_fc1, g_fc1);
    cudaGetSymbolAddress((void**)&p_fc1part, g_fc1part);
    cudaGetSymbolAddress((void**)&p_sp1, g_part1);
    cudaGetSymbolAddress((void**)&p_sp2, g_part2);
    cudaGetSymbolAddress((void**)&p_cpart, g_cpart);
    cudaGetSymbolAddress((void**)&p_scal, g_scal);

    // 1) conv-weight ternarize (batched)
    cw_abs_sum_kernel<<<dim3(CW_NB, 4), 256>>>(w1, w2, w3, w4, p_cpart);
    cw_delta_final_kernel<<<4, 128>>>(p_cpart, p_scal);
    cw_pack_kernel<<<1024, 256>>>(w1, w2, w3, w4, p_scal, pA1, pA2, pA3, pA4);

    // 2) FC deltas (float4 paths)
    {
        long n1 = (long)in_sizes[17];
        int nb1 = stats_nb(n1 / 4);
        abs_sum4_kernel<<<nb1, 256>>>((const float4*)fw1, n1 / 4, p_sp1);
        delta_final_kernel<<<1, 256>>>(p_sp1, nb1, 1.0f / (float)n1, scal_slot(4));
        long n2 = (long)in_sizes[19];
        int nb2 = stats_nb(n2 / 4);
        abs_sum4_kernel<<<nb2, 256>>>((const float4*)fw2, n2 / 4, p_sp1);
        delta_final_kernel<<<1, 256>>>(p_sp1, nb2, 1.0f / (float)n2, scal_slot(5));
        masked_sum4_kernel<<<nb2, 256>>>((const float4*)fw2, n2 / 4, scal_slot(5), p_sp1, p_sp2);
        alpha_final_kernel<<<1, 256>>>(p_sp1, p_sp2, nb2, scal_slot(5));
    }

    // 3) pack layer-1 input
    pack_x_kernel<<<2097152 / 256, 256>>>(x, p_xpack);

    // 4) conv blocks
    conv_layer(p_xpack, pA1, g1, be1, p_conv, p_pool, 4,   64,  32,   7, 14);
    conv_layer(p_pool,  pA2, g2, be2, p_conv, p_pool, 64,  128, 576,  6, 12);
    conv_layer(p_pool,  pA3, g3, be3, p_conv, p_pool, 128, 256, 1152, 5, 10);
    conv_layer(p_pool,  pA4, g4, be4, p_conv, p_pool, 256, 512, 2304, 4, 8);

    // 5) FC1 (split-K, inline ternarize + fused alpha stats) + alpha + relu
    fc1_partial_kernel<<<dim3(16, 16), 256>>>(p_pool, fw1, scal_slot(4), p_fc1part, p_sp1, p_sp2);
    alpha_final_kernel<<<1, 256>>>(p_sp1, p_sp2, 256, scal_slot(4));
    fc1_post_kernel<<<(32 * 1024 + 255) / 256, 256>>>(p_fc1part, fb1, scal_slot(4), p_fc1);

    // 6) FC2 -> output
    fc2_kernel<<<(32 * 1000 * 32 + 255) / 256, 256>>>(p_fc1, fw2, fb2, scal_slot(5), out);
}

// round 12
// speedup vs baseline: 1.7861x; 1.0356x over previous
#include <cuda_runtime.h>
#include <cuda_bf16.h>
#include <cstdint>

// ---------------------------------------------------------------------------
// TernaryCNN v8 (mma.sync path; tcgen05 unavailable — harness ptxas targets
// sm_103 without the 'a' feature suffix, rejecting all tcgen05 instructions):
//  - implicit-GEMM convs, split-bf16 packed activations, sign weights
//  - 128x128 block tile; fragments loaded via ldmatrix.x4 (B stored
//    pixel-major, same 128x36 padded layout as A -> conflict-free LDSM)
//  - BN stats fused in GEMM epilogue; pool emits packed activations
//  - FC1 float4/uint4 loads + fused ternary stats; batched conv-weight stats
// ---------------------------------------------------------------------------

#define N_BATCH 32

// -------------------- device scratch (static, no allocs) -------------------
__device__ float g_conv[33554432];        // conv out C-major [co][n][h][w]
__device__ uint32_t g_pool[8388608];      // pooled NCHW, packed (hi,lo)
__device__ uint32_t g_xpack[2097152];     // packed layer-1 input [32][4][16384]
__device__ uint32_t g_A1[2048];
__device__ uint32_t g_A2[73728];
__device__ uint32_t g_A3[294912];
__device__ uint32_t g_A4[1179648];
__device__ float g_fc1[32 * 1024];
__device__ float g_fc1part[16 * 32 * 1024];
__device__ float g_part1[512];
__device__ float g_part2[512];
__device__ float g_cpart[4 * 128];
__device__ float g_scal[32];              // 8 slots x 4
__device__ float g_bnp1[262144];
__device__ float g_bnp2[262144];
__device__ float g_bnscale[512];
__device__ float g_bnshift[512];

// ----------------------------- helpers -------------------------------------
__device__ __forceinline__ uint32_t pack_split(float x) {
    __nv_bfloat16 h = __float2bfloat16_rn(x);
    float hf = __bfloat162float(h);
    __nv_bfloat16 l = __float2bfloat16_rn(x - hf);
    return ((uint32_t)__bfloat16_as_ushort(l) << 16) | (uint32_t)__bfloat16_as_ushort(h);
}
__device__ __forceinline__ float unpack_split(uint32_t u) {
    __nv_bfloat16 h = __ushort_as_bfloat16((unsigned short)(u & 0xffff));
    __nv_bfloat16 l = __ushort_as_bfloat16((unsigned short)(u >> 16));
    return __bfloat162float(h) + __bfloat162float(l);
}

// ------------------- batched conv-weight ternarize --------------------------
#define CW_NB 128
__constant__ long c_cwn[4] = {1728, 73728, 294912, 1179648};

__global__ void cw_abs_sum_kernel(const float* __restrict__ w1, const float* __restrict__ w2,
                                  const float* __restrict__ w3, const float* __restrict__ w4,
                                  float* __restrict__ part) {
    __shared__ float sh[256];
    const int t = blockIdx.y;
    const float* w = (t == 0) ? w1 : (t == 1) ? w2 : (t == 2) ? w3 : w4;
    const long n = c_cwn[t];
    float a = 0.f;
    for (long i = (long)blockIdx.x * 256 + threadIdx.x; i < n; i += (long)CW_NB * 256)
        a += fabsf(w[i]);
    sh[threadIdx.x] = a; __syncthreads();
    for (int o = 128; o > 0; o >>= 1) {
        if (threadIdx.x < o) sh[threadIdx.x] += sh[threadIdx.x + o];
        __syncthreads();
    }
    if (threadIdx.x == 0) part[t * CW_NB + blockIdx.x] = sh[0];
}

__global__ void cw_delta_final_kernel(const float* __restrict__ part, float* __restrict__ scal) {
    __shared__ float sh[128];
    const int t = blockIdx.x;
    sh[threadIdx.x] = part[t * CW_NB + threadIdx.x];
    __syncthreads();
    for (int o = 64; o > 0; o >>= 1) {
        if (threadIdx.x < o) sh[threadIdx.x] += sh[threadIdx.x + o];
        __syncthreads();
    }
    if (threadIdx.x == 0) {
        float mean = sh[0] / (float)c_cwn[t];
        scal[4 * t] = 0.7f * mean;
        scal[4 * t + 2] = mean;
    }
}

__global__ void cw_pack_kernel(const float* __restrict__ w1, const float* __restrict__ w2,
                               const float* __restrict__ w3, const float* __restrict__ w4,
                               const float* __restrict__ scal,
                               uint32_t* __restrict__ o1, uint32_t* __restrict__ o2,
                               uint32_t* __restrict__ o3, uint32_t* __restrict__ o4) {
    const int total = 2048 + 73728 + 294912 + 1179648;
    for (int idx = blockIdx.x * 256 + threadIdx.x; idx < total; idx += gridDim.x * 256) {
        const float* w; uint32_t* o; float d; int K, Kpad; int j = idx;
        if (j < 2048) { w = w1; o = o1; d = scal[0]; K = 27; Kpad = 32; }
        else if ((j -= 2048) < 73728) { w = w2; o = o2; d = scal[4]; K = 576; Kpad = 576; }
        else if ((j -= 73728) < 294912) { w = w3; o = o3; d = scal[8]; K = 1152; Kpad = 1152; }
        else { j -= 294912; w = w4; o = o4; d = scal[12]; K = 2304; Kpad = 2304; }
        int co = j / Kpad;
        int kg = j - co * Kpad;
        float s = 0.f;
        if (kg < K) {
            float v = w[co * K + kg];
            s = (v > d) ? 1.f : ((v < -d) ? -1.f : 0.f);
        }
        uint32_t u = (uint32_t)__bfloat16_as_ushort(__float2bfloat16_rn(s));
        o[j] = u * 0x00010001u;
    }
}

// ----------------------------- fc stats (float4) ----------------------------
__global__ void abs_sum4_kernel(const float4* __restrict__ w, long n4, float* __restrict__ part) {
    __shared__ float sh[256];
    float a = 0.f;
    const long stride = (long)gridDim.x * 256;
    for (long i = (long)blockIdx.x * 256 + threadIdx.x; i < n4; i += stride) {
        float4 v = w[i];
        a += fabsf(v.x) + fabsf(v.y) + fabsf(v.z) + fabsf(v.w);
    }
    sh[threadIdx.x] = a; __syncthreads();
    for (int o = 128; o > 0; o >>= 1) {
        if (threadIdx.x < o) sh[threadIdx.x] += sh[threadIdx.x + o];
        __syncthreads();
    }
    if (threadIdx.x == 0) part[blockIdx.x] = sh[0];
}

__global__ void delta_final_kernel(const float* __restrict__ part, int nb, float inv_n,
                                   float* __restrict__ scal) {
    __shared__ float sh[256];
    float a = 0.f;
    for (int i = threadIdx.x; i < nb; i += 256) a += part[i];
    sh[threadIdx.x] = a; __syncthreads();
    for (int o = 128; o > 0; o >>= 1) {
        if (threadIdx.x < o) sh[threadIdx.x] += sh[threadIdx.x + o];
        __syncthreads();
    }
    if (threadIdx.x == 0) {
        float mean = sh[0] * inv_n;
        scal[0] = 0.7f * mean;
        scal[2] = mean;
    }
}

__global__ void masked_sum4_kernel(const float4* __restrict__ w, long n4, const float* __restrict__ scal,
                                   float* __restrict__ p1, float* __restrict__ p2) {
    __shared__ float sh1[256], sh2[256];
    const float delta = scal[0];
    const long stride = (long)gridDim.x * 256;
    float s = 0.f, c = 0.f;
    for (long i = (long)blockIdx.x * 256 + threadIdx.x; i < n4; i += stride) {
        float4 v = w[i];
        float a0 = fabsf(v.x), a1 = fabsf(v.y), a2 = fabsf(v.z), a3 = fabsf(v.w);
        if (a0 > delta) { s += a0; c += 1.f; }
        if (a1 > delta) { s += a1; c += 1.f; }
        if (a2 > delta) { s += a2; c += 1.f; }
        if (a3 > delta) { s += a3; c += 1.f; }
    }
    sh1[threadIdx.x] = s; sh2[threadIdx.x] = c; __syncthreads();
    for (int o = 128; o > 0; o >>= 1) {
        if (threadIdx.x < o) { sh1[threadIdx.x] += sh1[threadIdx.x + o]; sh2[threadIdx.x] += sh2[threadIdx.x + o]; }
        __syncthreads();
    }
    if (threadIdx.x == 0) { p1[blockIdx.x] = sh1[0]; p2[blockIdx.x] = sh2[0]; }
}

__global__ void alpha_final_kernel(const float* __restrict__ p1, const float* __restrict__ p2,
                                   int cnt, float* __restrict__ scal) {
    __shared__ float sh1[256], sh2[256];
    float s = 0.f, c = 0.f;
    for (int i = threadIdx.x; i < cnt; i += 256) { s += p1[i]; c += p2[i]; }
    sh1[threadIdx.x] = s; sh2[threadIdx.x] = c;
    __syncthreads();
    for (int o = 128; o > 0; o >>= 1) {
        if (threadIdx.x < o) { sh1[threadIdx.x] += sh1[threadIdx.x + o]; sh2[threadIdx.x] += sh2[threadIdx.x + o]; }
        __syncthreads();
    }
    if (threadIdx.x == 0)
        scal[1] = (sh2[0] > 0.f) ? (sh1[0] / sh2[0]) : scal[2];
}

__global__ void pack_x_kernel(const float* __restrict__ x, uint32_t* __restrict__ out) {
    int idx = blockIdx.x * 256 + threadIdx.x;
    int p = idx & 16383;
    int c = (idx >> 14) & 3;
    int n = idx >> 16;
    float v = 0.f;
    if (c < 3) v = x[((n * 3 + c) << 14) | p];
    out[idx] = pack_split(v);
}

// ----------------- implicit-GEMM conv (split-bf16, mma m16n8k16) ------------
// Templated on MI; MB = MI*32 rows per block. A and B both stored 36-uint32
// stride (pixel-major B) so all fragment loads are conflict-free ldmatrix.x4.
#define GNT 128
#define T_LD 36
#define BB_BUF (128 * T_LD)

__device__ __forceinline__ void mma_bf16(float& c0, float& c1, float& c2, float& c3,
                                         uint32_t a0, uint32_t a1, uint32_t a2, uint32_t a3,
                                         uint32_t b0, uint32_t b1) {
    asm volatile(
        "mma.sync.aligned.m16n8k16.row.col.f32.bf16.bf16.f32 "
        "{%0,%1,%2,%3}, {%4,%5,%6,%7}, {%8,%9}, {%0,%1,%2,%3};"
        : "+f"(c0), "+f"(c1), "+f"(c2), "+f"(c3)
        : "r"(a0), "r"(a1), "r"(a2), "r"(a3), "r"(b0), "r"(b1));
}

template <int MI>
__global__ void __launch_bounds__(256) gemm_conv_kernel(
    const uint32_t* __restrict__ A, const uint32_t* __restrict__ Xp, float* __restrict__ C,
    int CI, int nk, int lw, int lhw, int N, int nbx,
    float* __restrict__ bnp1, float* __restrict__ bnp2) {
    constexpr int MB = MI * 32;
    constexpr int SA_BUF = MB * T_LD;
    extern __shared__ uint32_t smem_u[];
    uint32_t* sA = smem_u;                        // 2 x SA_BUF
    uint32_t* sB = smem_u + 2 * SA_BUF;           // 2 x BB_BUF (pixel-major)
    float* sRed = (float*)(smem_u + 2 * SA_BUF + 2 * BB_BUF);   // [MB][4] x2

    const int tid = threadIdx.x;
    const int warp = tid >> 5, lane = tid & 31;
    const int wm = warp >> 2, wn = warp & 3;
    const int g = lane >> 2, tg = lane & 3;
    const int m0 = blockIdx.y * MB;
    const int n0 = blockIdx.x * GNT;
    const int Kpad = nk * 32;

    uint32_t sbase;
    asm("{ .reg .u64 t; cvta.to.shared.u64 t, %1; cvt.u32.u64 %0, t; }"
        : "=r"(sbase) : "l"(smem_u));
    // ldmatrix lane->row mapping (derived from the proven manual loads)
    const uint32_t aFrag = sbase
        + ((wm * (MI * 16) + (lane & 15)) * T_LD + ((lane >> 4) ? 4 : 0)) * 4;
    const uint32_t bFrag = sbase + 2 * SA_BUF * 4
        + ((wn * 32 + (lane & 7) + ((lane >> 4) ? 8 : 0)) * T_LD
           + (((lane >> 3) & 1) ? 4 : 0)) * 4;

    // fixed pixel per thread (B gather)
    const int col = tid & 127;
    const int khalf = tid >> 7;
    const int W = 1 << lw;
    const int H = 1 << (lhw - lw);
    const int p = n0 + col;
    const int hp = (p >> lw) & (H - 1);
    const int wp = p & (W - 1);
    const uint32_t* xb = Xp + (((long)(p >> lhw) * CI) << lhw);

    const int hmask = ((hp - 1 >= 0) ? 1 : 0) | 2 | ((hp + 1 < H) ? 4 : 0);
    const int wmask = ((wp - 1 >= 0) ? 1 : 0) | 2 | ((wp + 1 < W) ? 4 : 0);
    const int boff0 = ((hp - 1) << lw) + (wp - 1);

    float acc[MI][4][4];
#pragma unroll
    for (int mi = 0; mi < MI; mi++)
#pragma unroll
        for (int ni = 0; ni < 4; ni++)
#pragma unroll
            for (int q = 0; q < 4; q++) acc[mi][ni][q] = 0.f;

    uint4 rA[MI];
    uint32_t rbw[16];

    auto gload = [&](int kc) {
#pragma unroll
        for (int i = 0; i < MI; i++) {
            int q = tid + i * 256;
            int r = q >> 3, c4 = q & 7;
            rA[i] = *(const uint4*)&A[(long)(m0 + r) * Kpad + kc * 32 + c4 * 4];
        }
        int base = kc * 32 + 16 * khalf;
        int ci = base / 9;
        int rs = base - ci * 9;
        int rr = rs / 3;
        int ss = rs - rr * 3;
        int cioff = ci << lhw;
#pragma unroll
        for (int i = 0; i < 16; i++) {
            uint32_t v = 0;
            if (((hmask >> rr) & (wmask >> ss) & 1) != 0)
                v = xb[cioff + boff0 + (rr << lw) + ss];
            rbw[i] = v;
            if (++ss == 3) { ss = 0; if (++rr == 3) { rr = 0; cioff += 1 << lhw; } }
        }
    };
    auto sstore = [&](int buf) {
        uint32_t* dA = sA + buf * SA_BUF;
        uint32_t* dB = sB + buf * BB_BUF;
#pragma unroll
        for (int i = 0; i < MI; i++) {
            int q = tid + i * 256;
            int r = q >> 3, c4 = q & 7;
            *(uint4*)&dA[r * T_LD + c4 * 4] = rA[i];
        }
        const int rowb = col * T_LD + khalf * 16;
#pragma unroll
        for (int c = 0; c < 4; c++)
            *(uint4*)&dB[rowb + c * 4] =
                make_uint4(rbw[4 * c], rbw[4 * c + 1], rbw[4 * c + 2], rbw[4 * c + 3]);
    };

    gload(0);
    sstore(0);
    __syncthreads();

    for (int kc = 0; kc < nk; kc++) {
        const int buf = kc & 1;
        if (kc + 1 < nk) gload(kc + 1);

        const uint32_t aB = aFrag + buf * SA_BUF * 4;
        const uint32_t bB = bFrag + buf * BB_BUF * 4;
#pragma unroll
        for (int ks = 0; ks < 4; ks++) {
            uint32_t af[MI][4], bf[4][2];
#pragma unroll
            for (int mi = 0; mi < MI; mi++)
                asm volatile("ldmatrix.sync.aligned.m8n8.x4.shared.b16 {%0,%1,%2,%3}, [%4];"
                    : "=r"(af[mi][0]), "=r"(af[mi][1]), "=r"(af[mi][2]), "=r"(af[mi][3])
                    : "r"(aB + (mi * 16 * T_LD) * 4 + ks * 32));
#pragma unroll
            for (int q = 0; q < 2; q++)
                asm volatile("ldmatrix.sync.aligned.m8n8.x4.shared.b16 {%0,%1,%2,%3}, [%4];"
                    : "=r"(bf[2 * q][0]), "=r"(bf[2 * q][1]),
                      "=r"(bf[2 * q + 1][0]), "=r"(bf[2 * q + 1][1])
                    : "r"(bB + (q * 16 * T_LD) * 4 + ks * 32));
#pragma unroll
            for (int mi = 0; mi < MI; mi++)
#pragma unroll
                for (int ni = 0; ni < 4; ni++)
                    mma_bf16(acc[mi][ni][0], acc[mi][ni][1], acc[mi][ni][2], acc[mi][ni][3],
                             af[mi][0], af[mi][1], af[mi][2], af[mi][3],
                             bf[ni][0], bf[ni][1]);
        }
        if (kc + 1 < nk) sstore(buf ^ 1);
        __syncthreads();
    }

    // -------- epilogue: C store + fused BN partial stats --------
#pragma unroll
    for (int mi = 0; mi < MI; mi++) {
        const int row = m0 + wm * (MI * 16) + mi * 16 + g;
#pragma unroll
        for (int ni = 0; ni < 4; ni++) {
            const int colc = n0 + wn * 32 + ni * 8 + 2 * tg;
            float* p0 = &C[(long)row * N + colc];
            p0[0] = acc[mi][ni][0];
            p0[1] = acc[mi][ni][1];
            float* p1 = &C[(long)(row + 8) * N + colc];
            p1[0] = acc[mi][ni][2];
            p1[1] = acc[mi][ni][3];
        }
    }

#pragma unroll
    for (int mi = 0; mi < MI; mi++) {
        float a0 = 0.f, q0 = 0.f, a1 = 0.f, q1 = 0.f;
#pragma unroll
        for (int ni = 0; ni < 4; ni++) {
            a0 += acc[mi][ni][0] + acc[mi][ni][1];
            q0 += acc[mi][ni][0] * acc[mi][ni][0] + acc[mi][ni][1] * acc[mi][ni][1];
            a1 += acc[mi][ni][2] + acc[mi][ni][3];
            q1 += acc[mi][ni][2] * acc[mi][ni][2] + acc[mi][ni][3] * acc[mi][ni][3];
        }
#pragma unroll
        for (int off = 1; off <= 2; off <<= 1) {
            a0 += __shfl_xor_sync(0xffffffffu, a0, off);
            q0 += __shfl_xor_sync(0xffffffffu, q0, off);
            a1 += __shfl_xor_sync(0xffffffffu, a1, off);
            q1 += __shfl_xor_sync(0xffffffffu, q1, off);
        }
        if (tg == 0) {
            int r0 = wm * (MI * 16) + mi * 16 + g;
            sRed[r0 * 4 + wn] = a0;
            sRed[MB * 4 + r0 * 4 + wn] = q0;
            sRed[(r0 + 8) * 4 + wn] = a1;
            sRed[MB * 4 + (r0 + 8) * 4 + wn] = q1;
        }
    }
    __syncthreads();
    if (tid < MB) {
        float s = sRed[tid * 4] + sRed[tid * 4 + 1] + sRed[tid * 4 + 2] + sRed[tid * 4 + 3];
        float q = sRed[MB * 4 + tid * 4] + sRed[MB * 4 + tid * 4 + 1]
                + sRed[MB * 4 + tid * 4 + 2] + sRed[MB * 4 + tid * 4 + 3];
        bnp1[(long)(m0 + tid) * nbx + blockIdx.x] = s;
        bnp2[(long)(m0 + tid) * nbx + blockIdx.x] = q;
    }
}

// ------------------------------ batchnorm ----------------------------------
__global__ void bn_final_kernel(const float* __restrict__ p1, const float* __restrict__ p2,
                                int nbx, float invM,
                                const float* __restrict__ gamma, const float* __restrict__ beta,
                                float* __restrict__ scale, float* __restrict__ shift) {
    __shared__ float sh1[256], sh2[256];
    const int c = blockIdx.x;
    float s = 0.f, q = 0.f;
    for (int i = threadIdx.x; i < nbx; i += 256) {
        s += p1[(long)c * nbx + i];
        q += p2[(long)c * nbx + i];
    }
    sh1[threadIdx.x] = s; sh2[threadIdx.x] = q; __syncthreads();
    for (int o = 128; o > 0; o >>= 1) {
        if (threadIdx.x < o) { sh1[threadIdx.x] += sh1[threadIdx.x + o]; sh2[threadIdx.x] += sh2[threadIdx.x + o]; }
        __syncthreads();
    }
    if (threadIdx.x == 0) {
        float mean = sh1[0] * invM;
        float var = sh2[0] * invM - mean * mean;
        float istd = rsqrtf(var + 1e-5f);
        float sc = gamma[c] * istd;
        scale[c] = sc;
        shift[c] = beta[c] - mean * sc;
    }
}

__global__ void bn_relu_pool_cm_kernel(const float* __restrict__ y, const float* __restrict__ scale,
                                       const float* __restrict__ shift, uint32_t* __restrict__ out,
                                       int C, int H, int W, long total) {
    long idx = (long)blockIdx.x * 256 + threadIdx.x;
    if (idx >= total) return;
    const int W2 = W >> 1, H2 = H >> 1;
    int wo = (int)(idx % W2);
    long t = idx / W2;
    int ho = (int)(t % H2); t /= H2;
    int c = (int)(t % C);
    int n = (int)(t / C);
    const float* yp = y + (((long)c * N_BATCH + n) * H + 2 * ho) * W + 2 * wo;
    float sc = scale[c], sh = shift[c];
    float a = fmaxf(sc * yp[0] + sh, sc * yp[1] + sh);
    float b = fmaxf(sc * yp[W] + sh, sc * yp[W + 1] + sh);
    out[idx] = pack_split(fmaxf(fmaxf(a, b), 0.f));
}

// --------------------------------- FC --------------------------------------
__global__ void fc1_partial_kernel(const uint32_t* __restrict__ x, const float* __restrict__ w,
                                   const float* __restrict__ scal, float* __restrict__ part,
                                   float* __restrict__ sp1, float* __restrict__ sp2) {
    __shared__ float s_w[64][33];
    __shared__ __align__(16) float s_x[32][34];
    __shared__ float r1[256], r2[256];
    const int K = 32768;
    const int o0 = blockIdx.x * 64;
    const int k0 = blockIdx.y * 2048;
    const int tid = threadIdx.x;
    const int tx = tid & 15;
    const int ty = tid >> 4;
    const float d = scal[0];

    float acc[4][2];
#pragma unroll
    for (int i = 0; i < 4; i++) { acc[i][0] = 0.f; acc[i][1] = 0.f; }
    float ms = 0.f, mc = 0.f;

    for (int kk = k0; kk < k0 + 2048; kk += 32) {
#pragma unroll
        for (int t = 0; t < 2; t++) {
            int idx = tid + t * 256;
            int row = idx >> 3, c4 = idx & 7;
            float4 v = *(const float4*)&w[(long)(o0 + row) * K + kk + c4 * 4];
            float a0 = fabsf(v.x), a1 = fabsf(v.y), a2 = fabsf(v.z), a3 = fabsf(v.w);
            if (a0 > d) { ms += a0; mc += 1.f; }
            if (a1 > d) { ms += a1; mc += 1.f; }
            if (a2 > d) { ms += a2; mc += 1.f; }
            if (a3 > d) { ms += a3; mc += 1.f; }
            s_w[row][c4 * 4 + 0] = (v.x > d) ? 1.f : ((v.x < -d) ? -1.f : 0.f);
            s_w[row][c4 * 4 + 1] = (v.y > d) ? 1.f : ((v.y < -d) ? -1.f : 0.f);
            s_w[row][c4 * 4 + 2] = (v.z > d) ? 1.f : ((v.z < -d) ? -1.f : 0.f);
            s_w[row][c4 * 4 + 3] = (v.w > d) ? 1.f : ((v.w < -d) ? -1.f : 0.f);
        }
        {
            int b = tid >> 3, c4 = tid & 7;
            uint4 u = *(const uint4*)&x[(long)b * K + kk + c4 * 4];
            s_x[c4 * 4 + 0][b] = unpack_split(u.x);
            s_x[c4 * 4 + 1][b] = unpack_split(u.y);
            s_x[c4 * 4 + 2][b] = unpack_split(u.z);
            s_x[c4 * 4 + 3][b] = unpack_split(u.w);
        }
        __syncthreads();
#pragma unroll
        for (int j = 0; j < 32; j++) {
            float2 xv = *(const float2*)&s_x[j][tx * 2];
#pragma unroll
            for (int i = 0; i < 4; i++) {
                float wv = s_w[ty * 4 + i][j];
                acc[i][0] += wv * xv.x;
                acc[i][1] += wv * xv.y;
            }
        }
        __syncthreads();
    }
#pragma unroll
    for (int i = 0; i < 4; i++)
#pragma unroll
        for (int q = 0; q < 2; q++)
            part[((long)blockIdx.y * 32 + tx * 2 + q) * 1024 + o0 + ty * 4 + i] = acc[i][q];

    r1[tid] = ms; r2[tid] = mc; __syncthreads();
    for (int o = 128; o > 0; o >>= 1) {
        if (tid < o) { r1[tid] += r1[tid + o]; r2[tid] += r2[tid + o]; }
        __syncthreads();
    }
    if (tid == 0) {
        int slot = blockIdx.y * 16 + blockIdx.x;
        sp1[slot] = r1[0];
        sp2[slot] = r2[0];
    }
}

__global__ void fc1_post_kernel(const float* __restrict__ part, const float* __restrict__ bias,
                                const float* __restrict__ scal, float* __restrict__ out) {
    int idx = blockIdx.x * 256 + threadIdx.x;
    if (idx >= 32 * 1024) return;
    int o = idx & 1023;
    float s = 0.f;
#pragma unroll
    for (int ks = 0; ks < 16; ks++) s += part[(long)ks * 32 * 1024 + idx];
    out[idx] = fmaxf(s * scal[1] + bias[o], 0.f);
}

__global__ void fc2_kernel(const float* __restrict__ x, const float* __restrict__ w,
                           const float* __restrict__ bias, const float* __restrict__ scal,
                           float* __restrict__ out) {
    int gw = (blockIdx.x * 256 + threadIdx.x) >> 5;
    int lane = threadIdx.x & 31;
    if (gw >= 32 * 1000) return;
    int b = gw / 1000, o = gw % 1000;
    const float d = scal[0];
    float a = 0.f;
    for (int k = lane; k < 1024; k += 32) {
        float wv = w[o * 1024 + k];
        float sg = (wv > d) ? 1.f : ((wv < -d) ? -1.f : 0.f);
        a += x[b * 1024 + k] * sg;
    }
#pragma unroll
    for (int off = 16; off; off >>= 1) a += __shfl_down_sync(0xffffffffu, a, off);
    if (lane == 0) out[b * 1000 + o] = a * scal[1] + bias[o];
}

// ------------------------------- host side ---------------------------------
static float* scal_slot(int slot) {
    float* sc;
    cudaGetSymbolAddress((void**)&sc, g_scal);
    return sc + 4 * slot;
}

static int stats_nb(long n) {
    long nb = (n + 4095) / 4096;
    if (nb > 512) nb = 512;
    if (nb < 1) nb = 1;
    return (int)nb;
}

static void conv_layer(const uint32_t* xin, const uint32_t* Apack, const float* gamma, const float* beta,
                       float* conv_buf, uint32_t* pool_buf, int CI, int CO, int K, int lw, int lhw) {
    float *bp1, *bp2, *bsc, *bsh;
    cudaGetSymbolAddress((void**)&bp1, g_bnp1);
    cudaGetSymbolAddress((void**)&bp2, g_bnp2);
    cudaGetSymbolAddress((void**)&bsc, g_bnscale);
    cudaGetSymbolAddress((void**)&bsh, g_bnshift);

    const int N = N_BATCH << lhw;
    const int nk = (K + 31) / 32;
    const int nbx = N / GNT;

    if (CO >= 128) {
        constexpr int MB = 128;
        size_t smem = (size_t)(2 * MB * T_LD + 2 * BB_BUF + MB * 8) * 4;
        cudaFuncSetAttribute(gemm_conv_kernel<4>, cudaFuncAttributeMaxDynamicSharedMemorySize, (int)smem);
        gemm_conv_kernel<4><<<dim3(nbx, CO / MB), 256, smem>>>(Apack, xin, conv_buf,
                                                               CI, nk, lw, lhw, N, nbx, bp1, bp2);
    } else {
        constexpr int MB = 64;
        size_t smem = (size_t)(2 * MB * T_LD + 2 * BB_BUF + MB * 8) * 4;
        cudaFuncSetAttribute(gemm_conv_kernel<2>, cudaFuncAttributeMaxDynamicSharedMemorySize, (int)smem);
        gemm_conv_kernel<2><<<dim3(nbx, CO / MB), 256, smem>>>(Apack, xin, conv_buf,
                                                               CI, nk, lw, lhw, N, nbx, bp1, bp2);
    }

    const int H = 1 << (lhw - lw), Wd = 1 << lw;
    bn_final_kernel<<<CO, 256>>>(bp1, bp2, nbx, 1.0f / (float)N, gamma, beta, bsc, bsh);
    long total = (long)N_BATCH * CO * (H / 2) * (Wd / 2);
    bn_relu_pool_cm_kernel<<<(int)((total + 255) / 256), 256>>>(conv_buf, bsc, bsh, pool_buf,
                                                                CO, H, Wd, total);
}

extern "C" void kernel_launch(void* const* d_in, const int* in_sizes, int n_in,
                              void* d_out, int out_size) {
    const float* x   = (const float*)d_in[0];
    const float* w1  = (const float*)d_in[1];
    const float* g1  = (const float*)d_in[3];
    const float* be1 = (const float*)d_in[4];
    const float* w2  = (const float*)d_in[5];
    const float* g2  = (const float*)d_in[7];
    const float* be2 = (const float*)d_in[8];
    const float* w3  = (const float*)d_in[9];
    const float* g3  = (const float*)d_in[11];
    const float* be3 = (const float*)d_in[12];
    const float* w4  = (const float*)d_in[13];
    const float* g4  = (const float*)d_in[15];
    const float* be4 = (const float*)d_in[16];
    const float* fw1 = (const float*)d_in[17];
    const float* fb1 = (const float*)d_in[18];
    const float* fw2 = (const float*)d_in[19];
    const float* fb2 = (const float*)d_in[20];
    float* out = (float*)d_out;

    float *p_conv, *p_fc1, *p_fc1part, *p_sp1, *p_sp2, *p_cpart, *p_scal;
    uint32_t *p_pool, *p_xpack, *pA1, *pA2, *pA3, *pA4;
    cudaGetSymbolAddress((void**)&p_conv, g_conv);
    cudaGetSymbolAddress((void**)&p_pool, g_pool);
    cudaGetSymbolAddress((void**)&p_xpack, g_xpack);
    cudaGetSymbolAddress((void**)&pA1, g_A1);
    cudaGetSymbolAddress((void**)&pA2, g_A2);
    cudaGetSymbolAddress((void**)&pA3, g_A3);
    cudaGetSymbolAddress((void**)&pA4, g_A4);
    cudaGetSymbolAddress((void**)&p_fc1, g_fc1);
    cudaGetSymbolAddress((void**)&p_fc1part, g_fc1part);
    cudaGetSymbolAddress((void**)&p_sp1, g_part1);
    cudaGetSymbolAddress((void**)&p_sp2, g_part2);
    cudaGetSymbolAddress((void**)&p_cpart, g_cpart);
    cudaGetSymbolAddress((void**)&p_scal, g_scal);

    // 1) conv-weight ternarize (batched)
    cw_abs_sum_kernel<<<dim3(CW_NB, 4), 256>>>(w1, w2, w3, w4, p_cpart);
    cw_delta_final_kernel<<<4, 128>>>(p_cpart, p_scal);
    cw_pack_kernel<<<1024, 256>>>(w1, w2, w3, w4, p_scal, pA1, pA2, pA3, pA4);

    // 2) FC deltas (float4 paths)
    {
        long n1 = (long)in_sizes[17];
        int nb1 = stats_nb(n1 / 4);
        abs_sum4_kernel<<<nb1, 256>>>((const float4*)fw1, n1 / 4, p_sp1);
        delta_final_kernel<<<1, 256>>>(p_sp1, nb1, 1.0f / (float)n1, scal_slot(4));
        long n2 = (long)in_sizes[19];
        int nb2 = stats_nb(n2 / 4);
        abs_sum4_kernel<<<nb2, 256>>>((const float4*)fw2, n2 / 4, p_sp1);
        delta_final_kernel<<<1, 256>>>(p_sp1, nb2, 1.0f / (float)n2, scal_slot(5));
        masked_sum4_kernel<<<nb2, 256>>>((const float4*)fw2, n2 / 4, scal_slot(5), p_sp1, p_sp2);
        alpha_final_kernel<<<1, 256>>>(p_sp1, p_sp2, nb2, scal_slot(5));
    }

    // 3) pack layer-1 input
    pack_x_kernel<<<2097152 / 256, 256>>>(x, p_xpack);

    // 4) conv blocks
    conv_layer(p_xpack, pA1, g1, be1, p_conv, p_pool, 4,   64,  32,   7, 14);
    conv_layer(p_pool,  pA2, g2, be2, p_conv, p_pool, 64,  128, 576,  6, 12);
    conv_layer(p_pool,  pA3, g3, be3, p_conv, p_pool, 128, 256, 1152, 5, 10);
    conv_layer(p_pool,  pA4, g4, be4, p_conv, p_pool, 256, 512, 2304, 4, 8);

    // 5) FC1 (split-K, inline ternarize + fused alpha stats) + alpha + relu
    fc1_partial_kernel<<<dim3(16, 16), 256>>>(p_pool, fw1, scal_slot(4), p_fc1part, p_sp1, p_sp2);
    alpha_final_kernel<<<1, 256>>>(p_sp1, p_sp2, 256, scal_slot(4));
    fc1_post_kernel<<<(32 * 1024 + 255) / 256, 256>>>(p_fc1part, fb1, scal_slot(4), p_fc1);

    // 6) FC2 -> output
    fc2_kernel<<<(32 * 1000 * 32 + 255) / 256, 256>>>(p_fc1, fw2, fb2, scal_slot(5), out);
}

// round 16
// speedup vs baseline: 1.9205x; 1.0752x over previous
#include <cuda_runtime.h>
#include <cuda_fp16.h>
#include <cuda_bf16.h>
#include <cstdint>

// ---------------------------------------------------------------------------
// TernaryCNN v10: mixed-precision convs chosen by measured noise-per-cost.
//  - measured: each fp16-quantized conv input adds ~4.4e-4 RMS rel error
//    (4 layers -> 1.0039e-3 FAIL). Remove 2 contributions at minimal cost:
//    L1 split-bf16 (+0.9 G-MAC), L4 split-bf16 (+9.7 G); L2,L3 single-fp16.
//    Predicted rel_err ~7.9e-4, conv MMA work 40.4 G vs 61 G all-split.
//  - split kernel = R12 (proven @872us); fp16 kernel = v9 (proven correct)
//  - format chain: packed-split -> L1s -> fp16 -> L2h -> fp16 -> L3h ->
//    packed -> L4s -> packed -> FC1 (unchanged)
// ---------------------------------------------------------------------------

#define N_BATCH 32

// -------------------- device scratch (static, no allocs) -------------------
__device__ float g_conv[33554432];         // conv out C-major [co][n][h][w]
__device__ uint16_t g_pool[8388608];       // fp16 pooled (L1,L2 outputs)
__device__ uint32_t g_poolp[2097152];      // L3 pooled, split-bf16 packed
__device__ uint32_t g_pool4[1048576];      // L4 pooled, split-bf16 packed
__device__ uint32_t g_xpack[2097152];      // packed layer-1 input [32][4][16384]
__device__ uint32_t g_A1[2048];            // dup-bf16, 64 x 32
__device__ uint32_t g_A2[36864];           // fp16 pairs, 128 x 288
__device__ uint32_t g_A3[147456];          // fp16 pairs, 256 x 576
__device__ uint32_t g_A4[1179648];         // dup-bf16, 512 x 2304
__device__ float g_fc1[32 * 1024];
__device__ float g_fc1part[16 * 32 * 1024];
__device__ float g_part1[512];
__device__ float g_part2[512];
__device__ float g_cpart[4 * 128];
__device__ float g_scal[32];               // 8 slots x 4
__device__ float g_bnp1[262144];
__device__ float g_bnp2[262144];
__device__ float g_bnscale[512];
__device__ float g_bnshift[512];

// ----------------------------- helpers -------------------------------------
__device__ __forceinline__ uint32_t pack_split(float x) {
    __nv_bfloat16 h = __float2bfloat16_rn(x);
    float hf = __bfloat162float(h);
    __nv_bfloat16 l = __float2bfloat16_rn(x - hf);
    return ((uint32_t)__bfloat16_as_ushort(l) << 16) | (uint32_t)__bfloat16_as_ushort(h);
}
__device__ __forceinline__ float unpack_split(uint32_t u) {
    __nv_bfloat16 h = __ushort_as_bfloat16((unsigned short)(u & 0xffff));
    __nv_bfloat16 l = __ushort_as_bfloat16((unsigned short)(u >> 16));
    return __bfloat162float(h) + __bfloat162float(l);
}

// ------------------- batched conv-weight ternarize --------------------------
#define CW_NB 128
__constant__ long c_cwn[4] = {1728, 73728, 294912, 1179648};

__global__ void cw_abs_sum_kernel(const float* __restrict__ w1, const float* __restrict__ w2,
                                  const float* __restrict__ w3, const float* __restrict__ w4,
                                  float* __restrict__ part) {
    __shared__ float sh[256];
    const int t = blockIdx.y;
    const float* w = (t == 0) ? w1 : (t == 1) ? w2 : (t == 2) ? w3 : w4;
    const long n = c_cwn[t];
    float a = 0.f;
    for (long i = (long)blockIdx.x * 256 + threadIdx.x; i < n; i += (long)CW_NB * 256)
        a += fabsf(w[i]);
    sh[threadIdx.x] = a; __syncthreads();
    for (int o = 128; o > 0; o >>= 1) {
        if (threadIdx.x < o) sh[threadIdx.x] += sh[threadIdx.x + o];
        __syncthreads();
    }
    if (threadIdx.x == 0) part[t * CW_NB + blockIdx.x] = sh[0];
}

__global__ void cw_delta_final_kernel(const float* __restrict__ part, float* __restrict__ scal) {
    __shared__ float sh[128];
    const int t = blockIdx.x;
    sh[threadIdx.x] = part[t * CW_NB + threadIdx.x];
    __syncthreads();
    for (int o = 64; o > 0; o >>= 1) {
        if (threadIdx.x < o) sh[threadIdx.x] += sh[threadIdx.x + o];
        __syncthreads();
    }
    if (threadIdx.x == 0) {
        float mean = sh[0] / (float)c_cwn[t];
        scal[4 * t] = 0.7f * mean;
        scal[4 * t + 2] = mean;
    }
}

// pack: seg1 dup-bf16 (1 k/word), seg2/seg3 fp16 pairs (2 k/word), seg4 dup-bf16
__global__ void cw_pack_kernel(const float* __restrict__ w1, const float* __restrict__ w2,
                               const float* __restrict__ w3, const float* __restrict__ w4,
                               const float* __restrict__ scal,
                               uint32_t* __restrict__ o1, uint32_t* __restrict__ o2,
                               uint32_t* __restrict__ o3, uint32_t* __restrict__ o4) {
    const int total = 2048 + 36864 + 147456 + 1179648;
    for (int idx = blockIdx.x * 256 + threadIdx.x; idx < total; idx += gridDim.x * 256) {
        const float* w; uint32_t* o; float d; int K, wpr, pairs; int j = idx;
        if (j < 2048) { w = w1; o = o1; d = scal[0]; K = 27; wpr = 32; pairs = 0; }
        else if ((j -= 2048) < 36864) { w = w2; o = o2; d = scal[4]; K = 576; wpr = 288; pairs = 1; }
        else if ((j -= 36864) < 147456) { w = w3; o = o3; d = scal[8]; K = 1152; wpr = 576; pairs = 1; }
        else { j -= 147456; w = w4; o = o4; d = scal[12]; K = 2304; wpr = 2304; pairs = 0; }
        int co = j / wpr;
        int kg0 = j - co * wpr;
        uint32_t u;
        if (pairs) {
            u = 0;
#pragma unroll
            for (int q = 0; q < 2; q++) {
                int kg = kg0 * 2 + q;
                float s = 0.f;
                if (kg < K) {
                    float v = w[co * K + kg];
                    s = (v > d) ? 1.f : ((v < -d) ? -1.f : 0.f);
                }
                u |= (uint32_t)__half_as_ushort(__float2half_rn(s)) << (16 * q);
            }
        } else {
            float s = 0.f;
            if (kg0 < K) {
                float v = w[co * K + kg0];
                s = (v > d) ? 1.f : ((v < -d) ? -1.f : 0.f);
            }
            u = (uint32_t)__bfloat16_as_ushort(__float2bfloat16_rn(s)) * 0x00010001u;
        }
        o[j] = u;
    }
}

// ----------------------------- fc stats (float4) ----------------------------
__global__ void abs_sum4_kernel(const float4* __restrict__ w, long n4, float* __restrict__ part) {
    __shared__ float sh[256];
    float a = 0.f;
    const long stride = (long)gridDim.x * 256;
    for (long i = (long)blockIdx.x * 256 + threadIdx.x; i < n4; i += stride) {
        float4 v = w[i];
        a += fabsf(v.x) + fabsf(v.y) + fabsf(v.z) + fabsf(v.w);
    }
    sh[threadIdx.x] = a; __syncthreads();
    for (int o = 128; o > 0; o >>= 1) {
        if (threadIdx.x < o) sh[threadIdx.x] += sh[threadIdx.x + o];
        __syncthreads();
    }
    if (threadIdx.x == 0) part[blockIdx.x] = sh[0];
}

__global__ void delta_final_kernel(const float* __restrict__ part, int nb, float inv_n,
                                   float* __restrict__ scal) {
    __shared__ float sh[256];
    float a = 0.f;
    for (int i = threadIdx.x; i < nb; i += 256) a += part[i];
    sh[threadIdx.x] = a; __syncthreads();
    for (int o = 128; o > 0; o >>= 1) {
        if (threadIdx.x < o) sh[threadIdx.x] += sh[threadIdx.x + o];
        __syncthreads();
    }
    if (threadIdx.x == 0) {
        float mean = sh[0] * inv_n;
        scal[0] = 0.7f * mean;
        scal[2] = mean;
    }
}

__global__ void masked_sum4_kernel(const float4* __restrict__ w, long n4, const float* __restrict__ scal,
                                   float* __restrict__ p1, float* __restrict__ p2) {
    __shared__ float sh1[256], sh2[256];
    const float delta = scal[0];
    const long stride = (long)gridDim.x * 256;
    float s = 0.f, c = 0.f;
    for (long i = (long)blockIdx.x * 256 + threadIdx.x; i < n4; i += stride) {
        float4 v = w[i];
        float a0 = fabsf(v.x), a1 = fabsf(v.y), a2 = fabsf(v.z), a3 = fabsf(v.w);
        if (a0 > delta) { s += a0; c += 1.f; }
        if (a1 > delta) { s += a1; c += 1.f; }
        if (a2 > delta) { s += a2; c += 1.f; }
        if (a3 > delta) { s += a3; c += 1.f; }
    }
    sh1[threadIdx.x] = s; sh2[threadIdx.x] = c; __syncthreads();
    for (int o = 128; o > 0; o >>= 1) {
        if (threadIdx.x < o) { sh1[threadIdx.x] += sh1[threadIdx.x + o]; sh2[threadIdx.x] += sh2[threadIdx.x + o]; }
        __syncthreads();
    }
    if (threadIdx.x == 0) { p1[blockIdx.x] = sh1[0]; p2[blockIdx.x] = sh2[0]; }
}

__global__ void alpha_final_kernel(const float* __restrict__ p1, const float* __restrict__ p2,
                                   int cnt, float* __restrict__ scal) {
    __shared__ float sh1[256], sh2[256];
    float s = 0.f, c = 0.f;
    for (int i = threadIdx.x; i < cnt; i += 256) { s += p1[i]; c += p2[i]; }
    sh1[threadIdx.x] = s; sh2[threadIdx.x] = c;
    __syncthreads();
    for (int o = 128; o > 0; o >>= 1) {
        if (threadIdx.x < o) { sh1[threadIdx.x] += sh1[threadIdx.x + o]; sh2[threadIdx.x] += sh2[threadIdx.x + o]; }
        __syncthreads();
    }
    if (threadIdx.x == 0)
        scal[1] = (sh2[0] > 0.f) ? (sh1[0] / sh2[0]) : scal[2];
}

// pack layer-1 input: split-bf16 uint32, [32][4][16384] (channel 3 zero)
__global__ void pack_x_kernel(const float* __restrict__ x, uint32_t* __restrict__ out) {
    int idx = blockIdx.x * 256 + threadIdx.x;
    int p = idx & 16383;
    int c = (idx >> 14) & 3;
    int n = idx >> 16;
    float v = 0.f;
    if (c < 3) v = x[((n * 3 + c) << 14) | p];
    out[idx] = pack_split(v);
}

// --------------------- shared GEMM geometry / mma ---------------------------
#define GNT 128
#define T_LD 36
#define BB_BUF (128 * T_LD)

__device__ __forceinline__ void mma_bf16(float& c0, float& c1, float& c2, float& c3,
                                         uint32_t a0, uint32_t a1, uint32_t a2, uint32_t a3,
                                         uint32_t b0, uint32_t b1) {
    asm volatile(
        "mma.sync.aligned.m16n8k16.row.col.f32.bf16.bf16.f32 "
        "{%0,%1,%2,%3}, {%4,%5,%6,%7}, {%8,%9}, {%0,%1,%2,%3};"
        : "+f"(c0), "+f"(c1), "+f"(c2), "+f"(c3)
        : "r"(a0), "r"(a1), "r"(a2), "r"(a3), "r"(b0), "r"(b1));
}
__device__ __forceinline__ void mma_f16(float& c0, float& c1, float& c2, float& c3,
                                        uint32_t a0, uint32_t a1, uint32_t a2, uint32_t a3,
                                        uint32_t b0, uint32_t b1) {
    asm volatile(
        "mma.sync.aligned.m16n8k16.row.col.f32.f16.f16.f32 "
        "{%0,%1,%2,%3}, {%4,%5,%6,%7}, {%8,%9}, {%0,%1,%2,%3};"
        : "+f"(c0), "+f"(c1), "+f"(c2), "+f"(c3)
        : "r"(a0), "r"(a1), "r"(a2), "r"(a3), "r"(b0), "r"(b1));
}

// ----------- split-bf16 implicit-GEMM conv (R12, proven @872us) -------------
template <int MI>
__global__ void __launch_bounds__(256) gemm_split_kernel(
    const uint32_t* __restrict__ A, const uint32_t* __restrict__ Xp, float* __restrict__ C,
    int CI, int nk, int lw, int lhw, int N, int nbx,
    float* __restrict__ bnp1, float* __restrict__ bnp2) {
    constexpr int MB = MI * 32;
    constexpr int SA_BUF = MB * T_LD;
    extern __shared__ uint32_t smem_u[];
    uint32_t* sA = smem_u;
    uint32_t* sB = smem_u + 2 * SA_BUF;
    float* sRed = (float*)(smem_u + 2 * SA_BUF + 2 * BB_BUF);

    const int tid = threadIdx.x;
    const int warp = tid >> 5, lane = tid & 31;
    const int wm = warp >> 2, wn = warp & 3;
    const int g = lane >> 2, tg = lane & 3;
    const int m0 = blockIdx.y * MB;
    const int n0 = blockIdx.x * GNT;
    const int Kpad = nk * 32;

    uint32_t sbase;
    asm("{ .reg .u64 t; cvta.to.shared.u64 t, %1; cvt.u32.u64 %0, t; }"
        : "=r"(sbase) : "l"(smem_u));
    const uint32_t aFrag = sbase
        + ((wm * (MI * 16) + (lane & 15)) * T_LD + ((lane >> 4) ? 4 : 0)) * 4;
    const uint32_t bFrag = sbase + 2 * SA_BUF * 4
        + ((wn * 32 + (lane & 7) + ((lane >> 4) ? 8 : 0)) * T_LD
           + (((lane >> 3) & 1) ? 4 : 0)) * 4;

    const int col = tid & 127;
    const int khalf = tid >> 7;
    const int W = 1 << lw;
    const int H = 1 << (lhw - lw);
    const int p = n0 + col;
    const int hp = (p >> lw) & (H - 1);
    const int wp = p & (W - 1);
    const uint32_t* xb = Xp + (((long)(p >> lhw) * CI) << lhw);

    const int hmask = ((hp - 1 >= 0) ? 1 : 0) | 2 | ((hp + 1 < H) ? 4 : 0);
    const int wmask = ((wp - 1 >= 0) ? 1 : 0) | 2 | ((wp + 1 < W) ? 4 : 0);
    const int boff0 = ((hp - 1) << lw) + (wp - 1);

    float acc[MI][4][4];
#pragma unroll
    for (int mi = 0; mi < MI; mi++)
#pragma unroll
        for (int ni = 0; ni < 4; ni++)
#pragma unroll
            for (int q = 0; q < 4; q++) acc[mi][ni][q] = 0.f;

    uint4 rA[MI];
    uint32_t rbw[16];

    auto gload = [&](int kc) {
#pragma unroll
        for (int i = 0; i < MI; i++) {
            int q = tid + i * 256;
            int r = q >> 3, c4 = q & 7;
            rA[i] = *(const uint4*)&A[(long)(m0 + r) * Kpad + kc * 32 + c4 * 4];
        }
        int base = kc * 32 + 16 * khalf;
        int ci = base / 9;
        int rs = base - ci * 9;
        int rr = rs / 3;
        int ss = rs - rr * 3;
        int cioff = ci << lhw;
#pragma unroll
        for (int i = 0; i < 16; i++) {
            uint32_t v = 0;
            if (((hmask >> rr) & (wmask >> ss) & 1) != 0)
                v = xb[cioff + boff0 + (rr << lw) + ss];
            rbw[i] = v;
            if (++ss == 3) { ss = 0; if (++rr == 3) { rr = 0; cioff += 1 << lhw; } }
        }
    };
    auto sstore = [&](int buf) {
        uint32_t* dA = sA + buf * SA_BUF;
        uint32_t* dB = sB + buf * BB_BUF;
#pragma unroll
        for (int i = 0; i < MI; i++) {
            int q = tid + i * 256;
            int r = q >> 3, c4 = q & 7;
            *(uint4*)&dA[r * T_LD + c4 * 4] = rA[i];
        }
        const int rowb = col * T_LD + khalf * 16;
#pragma unroll
        for (int c = 0; c < 4; c++)
            *(uint4*)&dB[rowb + c * 4] =
                make_uint4(rbw[4 * c], rbw[4 * c + 1], rbw[4 * c + 2], rbw[4 * c + 3]);
    };

    gload(0);
    sstore(0);
    __syncthreads();

    for (int kc = 0; kc < nk; kc++) {
        const int buf = kc & 1;
        if (kc + 1 < nk) gload(kc + 1);

        const uint32_t aB = aFrag + buf * SA_BUF * 4;
        const uint32_t bB = bFrag + buf * BB_BUF * 4;
#pragma unroll
        for (int ks = 0; ks < 4; ks++) {
            uint32_t af[MI][4], bf[4][2];
#pragma unroll
            for (int mi = 0; mi < MI; mi++)
                asm volatile("ldmatrix.sync.aligned.m8n8.x4.shared.b16 {%0,%1,%2,%3}, [%4];"
                    : "=r"(af[mi][0]), "=r"(af[mi][1]), "=r"(af[mi][2]), "=r"(af[mi][3])
                    : "r"(aB + (mi * 16 * T_LD) * 4 + ks * 32));
#pragma unroll
            for (int q = 0; q < 2; q++)
                asm volatile("ldmatrix.sync.aligned.m8n8.x4.shared.b16 {%0,%1,%2,%3}, [%4];"
                    : "=r"(bf[2 * q][0]), "=r"(bf[2 * q][1]),
                      "=r"(bf[2 * q + 1][0]), "=r"(bf[2 * q + 1][1])
                    : "r"(bB + (q * 16 * T_LD) * 4 + ks * 32));
#pragma unroll
            for (int mi = 0; mi < MI; mi++)
#pragma unroll
                for (int ni = 0; ni < 4; ni++)
                    mma_bf16(acc[mi][ni][0], acc[mi][ni][1], acc[mi][ni][2], acc[mi][ni][3],
                             af[mi][0], af[mi][1], af[mi][2], af[mi][3],
                             bf[ni][0], bf[ni][1]);
        }
        if (kc + 1 < nk) sstore(buf ^ 1);
        __syncthreads();
    }

#pragma unroll
    for (int mi = 0; mi < MI; mi++) {
        const int row = m0 + wm * (MI * 16) + mi * 16 + g;
#pragma unroll
        for (int ni = 0; ni < 4; ni++) {
            const int colc = n0 + wn * 32 + ni * 8 + 2 * tg;
            float* p0 = &C[(long)row * N + colc];
            p0[0] = acc[mi][ni][0];
            p0[1] = acc[mi][ni][1];
            float* p1 = &C[(long)(row + 8) * N + colc];
            p1[0] = acc[mi][ni][2];
            p1[1] = acc[mi][ni][3];
        }
    }

#pragma unroll
    for (int mi = 0; mi < MI; mi++) {
        float a0 = 0.f, q0 = 0.f, a1 = 0.f, q1 = 0.f;
#pragma unroll
        for (int ni = 0; ni < 4; ni++) {
            a0 += acc[mi][ni][0] + acc[mi][ni][1];
            q0 += acc[mi][ni][0] * acc[mi][ni][0] + acc[mi][ni][1] * acc[mi][ni][1];
            a1 += acc[mi][ni][2] + acc[mi][ni][3];
            q1 += acc[mi][ni][2] * acc[mi][ni][2] + acc[mi][ni][3] * acc[mi][ni][3];
        }
#pragma unroll
        for (int off = 1; off <= 2; off <<= 1) {
            a0 += __shfl_xor_sync(0xffffffffu, a0, off);
            q0 += __shfl_xor_sync(0xffffffffu, q0, off);
            a1 += __shfl_xor_sync(0xffffffffu, a1, off);
            q1 += __shfl_xor_sync(0xffffffffu, q1, off);
        }
        if (tg == 0) {
            int r0 = wm * (MI * 16) + mi * 16 + g;
            sRed[r0 * 4 + wn] = a0;
            sRed[MB * 4 + r0 * 4 + wn] = q0;
            sRed[(r0 + 8) * 4 + wn] = a1;
            sRed[MB * 4 + (r0 + 8) * 4 + wn] = q1;
        }
    }
    __syncthreads();
    if (tid < MB) {
        float s = sRed[tid * 4] + sRed[tid * 4 + 1] + sRed[tid * 4 + 2] + sRed[tid * 4 + 3];
        float q = sRed[MB * 4 + tid * 4] + sRed[MB * 4 + tid * 4 + 1]
                + sRed[MB * 4 + tid * 4 + 2] + sRed[MB * 4 + tid * 4 + 3];
        bnp1[(long)(m0 + tid) * nbx + blockIdx.x] = s;
        bnp2[(long)(m0 + tid) * nbx + blockIdx.x] = q;
    }
}

// ------------- fp16 implicit-GEMM conv (v9, proven correct) -----------------
template <int MI>
__global__ void __launch_bounds__(256) gemm_h_kernel(
    const uint32_t* __restrict__ A, const uint16_t* __restrict__ Xp, float* __restrict__ C,
    int CI, int nk, int lw, int lhw, int N, int nbx,
    float* __restrict__ bnp1, float* __restrict__ bnp2) {
    constexpr int MB = MI * 32;
    constexpr int SA_BUF = MB * T_LD;
    extern __shared__ uint32_t smem_u[];
    uint32_t* sA = smem_u;
    uint32_t* sB = smem_u + 2 * SA_BUF;
    float* sRed = (float*)(smem_u + 2 * SA_BUF + 2 * BB_BUF);

    const int tid = threadIdx.x;
    const int warp = tid >> 5, lane = tid & 31;
    const int wm = warp >> 2, wn = warp & 3;
    const int g = lane >> 2, tg = lane & 3;
    const int m0 = blockIdx.y * MB;
    const int n0 = blockIdx.x * GNT;
    const int Kw = nk * 32;

    uint32_t sbase;
    asm("{ .reg .u64 t; cvta.to.shared.u64 t, %1; cvt.u32.u64 %0, t; }"
        : "=r"(sbase) : "l"(smem_u));
    const uint32_t aFrag = sbase
        + ((wm * (MI * 16) + (lane & 15)) * T_LD + ((lane >> 4) ? 4 : 0)) * 4;
    const uint32_t bFrag = sbase + 2 * SA_BUF * 4
        + ((wn * 32 + (lane & 7) + ((lane >> 4) ? 8 : 0)) * T_LD
           + (((lane >> 3) & 1) ? 4 : 0)) * 4;

    const int col = tid & 127;
    const int khalf = tid >> 7;
    const int W = 1 << lw;
    const int H = 1 << (lhw - lw);
    const int p = n0 + col;
    const int hp = (p >> lw) & (H - 1);
    const int wp = p & (W - 1);
    const uint16_t* xb = Xp + (((long)(p >> lhw) * CI) << lhw);

    const int hmask = ((hp - 1 >= 0) ? 1 : 0) | 2 | ((hp + 1 < H) ? 4 : 0);
    const int wmask = ((wp - 1 >= 0) ? 1 : 0) | 2 | ((wp + 1 < W) ? 4 : 0);
    const int boff0 = ((hp - 1) << lw) + (wp - 1);

    float acc[MI][4][4];
#pragma unroll
    for (int mi = 0; mi < MI; mi++)
#pragma unroll
        for (int ni = 0; ni < 4; ni++)
#pragma unroll
            for (int q = 0; q < 4; q++) acc[mi][ni][q] = 0.f;

    uint4 rA[MI];
    uint32_t rbw[16];

    auto gload = [&](int kc) {
#pragma unroll
        for (int i = 0; i < MI; i++) {
            int q = tid + i * 256;
            int r = q >> 3, c4 = q & 7;
            rA[i] = *(const uint4*)&A[(long)(m0 + r) * Kw + kc * 32 + c4 * 4];
        }
        int kidx = kc * 64 + 32 * khalf;
        int ci = kidx / 9;
        int rs = kidx - ci * 9;
        int rr = rs / 3;
        int ss = rs - rr * 3;
        int cioff = ci << lhw;
        uint32_t cur = 0;
#pragma unroll
        for (int i = 0; i < 32; i++) {
            uint16_t v = 0;
            if (((hmask >> rr) & (wmask >> ss) & 1) != 0)
                v = xb[cioff + boff0 + (rr << lw) + ss];
            if ((i & 1) == 0) cur = v;
            else rbw[i >> 1] = cur | ((uint32_t)v << 16);
            if (++ss == 3) { ss = 0; if (++rr == 3) { rr = 0; cioff += 1 << lhw; } }
        }
    };
    auto sstore = [&](int buf) {
        uint32_t* dA = sA + buf * SA_BUF;
        uint32_t* dB = sB + buf * BB_BUF;
#pragma unroll
        for (int i = 0; i < MI; i++) {
            int q = tid + i * 256;
            int r = q >> 3, c4 = q & 7;
            *(uint4*)&dA[r * T_LD + c4 * 4] = rA[i];
        }
        const int rowb = col * T_LD + khalf * 16;
#pragma unroll
        for (int c = 0; c < 4; c++)
            *(uint4*)&dB[rowb + c * 4] =
                make_uint4(rbw[4 * c], rbw[4 * c + 1], rbw[4 * c + 2], rbw[4 * c + 3]);
    };

    gload(0);
    sstore(0);
    __syncthreads();

    for (int kc = 0; kc < nk; kc++) {
        const int buf = kc & 1;
        if (kc + 1 < nk) gload(kc + 1);

        const uint32_t aB = aFrag + buf * SA_BUF * 4;
        const uint32_t bB = bFrag + buf * BB_BUF * 4;
#pragma unroll
        for (int ks = 0; ks < 4; ks++) {
            uint32_t af[MI][4], bf[4][2];
#pragma unroll
            for (int mi = 0; mi < MI; mi++)
                asm volatile("ldmatrix.sync.aligned.m8n8.x4.shared.b16 {%0,%1,%2,%3}, [%4];"
                    : "=r"(af[mi][0]), "=r"(af[mi][1]), "=r"(af[mi][2]), "=r"(af[mi][3])
                    : "r"(aB + (mi * 16 * T_LD) * 4 + ks * 32));
#pragma unroll
            for (int q = 0; q < 2; q++)
                asm volatile("ldmatrix.sync.aligned.m8n8.x4.shared.b16 {%0,%1,%2,%3}, [%4];"
                    : "=r"(bf[2 * q][0]), "=r"(bf[2 * q][1]),
                      "=r"(bf[2 * q + 1][0]), "=r"(bf[2 * q + 1][1])
                    : "r"(bB + (q * 16 * T_LD) * 4 + ks * 32));
#pragma unroll
            for (int mi = 0; mi < MI; mi++)
#pragma unroll
                for (int ni = 0; ni < 4; ni++)
                    mma_f16(acc[mi][ni][0], acc[mi][ni][1], acc[mi][ni][2], acc[mi][ni][3],
                            af[mi][0], af[mi][1], af[mi][2], af[mi][3],
                            bf[ni][0], bf[ni][1]);
        }
        if (kc + 1 < nk) sstore(buf ^ 1);
        __syncthreads();
    }

#pragma unroll
    for (int mi = 0; mi < MI; mi++) {
        const int row = m0 + wm * (MI * 16) + mi * 16 + g;
#pragma unroll
        for (int ni = 0; ni < 4; ni++) {
            const int colc = n0 + wn * 32 + ni * 8 + 2 * tg;
            float* p0 = &C[(long)row * N + colc];
            p0[0] = acc[mi][ni][0];
            p0[1] = acc[mi][ni][1];
            float* p1 = &C[(long)(row + 8) * N + colc];
            p1[0] = acc[mi][ni][2];
            p1[1] = acc[mi][ni][3];
        }
    }

#pragma unroll
    for (int mi = 0; mi < MI; mi++) {
        float a0 = 0.f, q0 = 0.f, a1 = 0.f, q1 = 0.f;
#pragma unroll
        for (int ni = 0; ni < 4; ni++) {
            a0 += acc[mi][ni][0] + acc[mi][ni][1];
            q0 += acc[mi][ni][0] * acc[mi][ni][0] + acc[mi][ni][1] * acc[mi][ni][1];
            a1 += acc[mi][ni][2] + acc[mi][ni][3];
            q1 += acc[mi][ni][2] * acc[mi][ni][2] + acc[mi][ni][3] * acc[mi][ni][3];
        }
#pragma unroll
        for (int off = 1; off <= 2; off <<= 1) {
            a0 += __shfl_xor_sync(0xffffffffu, a0, off);
            q0 += __shfl_xor_sync(0xffffffffu, q0, off);
            a1 += __shfl_xor_sync(0xffffffffu, a1, off);
            q1 += __shfl_xor_sync(0xffffffffu, q1, off);
        }
        if (tg == 0) {
            int r0 = wm * (MI * 16) + mi * 16 + g;
            sRed[r0 * 4 + wn] = a0;
            sRed[MB * 4 + r0 * 4 + wn] = q0;
            sRed[(r0 + 8) * 4 + wn] = a1;
            sRed[MB * 4 + (r0 + 8) * 4 + wn] = q1;
        }
    }
    __syncthreads();
    if (tid < MB) {
        float s = sRed[tid * 4] + sRed[tid * 4 + 1] + sRed[tid * 4 + 2] + sRed[tid * 4 + 3];
        float q = sRed[MB * 4 + tid * 4] + sRed[MB * 4 + tid * 4 + 1]
                + sRed[MB * 4 + tid * 4 + 2] + sRed[MB * 4 + tid * 4 + 3];
        bnp1[(long)(m0 + tid) * nbx + blockIdx.x] = s;
        bnp2[(long)(m0 + tid) * nbx + blockIdx.x] = q;
    }
}

// ------------------------------ batchnorm ----------------------------------
__global__ void bn_final_kernel(const float* __restrict__ p1, const float* __restrict__ p2,
                                int nbx, float invM,
                                const float* __restrict__ gamma, const float* __restrict__ beta,
                                float* __restrict__ scale, float* __restrict__ shift) {
    __shared__ float sh1[256], sh2[256];
    const int c = blockIdx.x;
    float s = 0.f, q = 0.f;
    for (int i = threadIdx.x; i < nbx; i += 256) {
        s += p1[(long)c * nbx + i];
        q += p2[(long)c * nbx + i];
    }
    sh1[threadIdx.x] = s; sh2[threadIdx.x] = q; __syncthreads();
    for (int o = 128; o > 0; o >>= 1) {
        if (threadIdx.x < o) { sh1[threadIdx.x] += sh1[threadIdx.x + o]; sh2[threadIdx.x] += sh2[threadIdx.x + o]; }
        __syncthreads();
    }
    if (threadIdx.x == 0) {
        float mean = sh1[0] * invM;
        float var = sh2[0] * invM - mean * mean;
        float istd = rsqrtf(var + 1e-5f);
        float sc = gamma[c] * istd;
        scale[c] = sc;
        shift[c] = beta[c] - mean * sc;
    }
}

__global__ void bn_relu_pool_h_kernel(const float* __restrict__ y, const float* __restrict__ scale,
                                      const float* __restrict__ shift, uint16_t* __restrict__ out,
                                      int C, int H, int W, long total) {
    long idx = (long)blockIdx.x * 256 + threadIdx.x;
    if (idx >= total) return;
    const int W2 = W >> 1, H2 = H >> 1;
    int wo = (int)(idx % W2);
    long t = idx / W2;
    int ho = (int)(t % H2); t /= H2;
    int c = (int)(t % C);
    int n = (int)(t / C);
    const float* yp = y + (((long)c * N_BATCH + n) * H + 2 * ho) * W + 2 * wo;
    float sc = scale[c], sh = shift[c];
    float a = fmaxf(sc * yp[0] + sh, sc * yp[1] + sh);
    float b = fmaxf(sc * yp[W] + sh, sc * yp[W + 1] + sh);
    out[idx] = __half_as_ushort(__float2half_rn(fmaxf(fmaxf(a, b), 0.f)));
}

__global__ void bn_relu_pool_p_kernel(const float* __restrict__ y, const float* __restrict__ scale,
                                      const float* __restrict__ shift, uint32_t* __restrict__ out,
                                      int C, int H, int W, long total) {
    long idx = (long)blockIdx.x * 256 + threadIdx.x;
    if (idx >= total) return;
    const int W2 = W >> 1, H2 = H >> 1;
    int wo = (int)(idx % W2);
    long t = idx / W2;
    int ho = (int)(t % H2); t /= H2;
    int c = (int)(t % C);
    int n = (int)(t / C);
    const float* yp = y + (((long)c * N_BATCH + n) * H + 2 * ho) * W + 2 * wo;
    float sc = scale[c], sh = shift[c];
    float a = fmaxf(sc * yp[0] + sh, sc * yp[1] + sh);
    float b = fmaxf(sc * yp[W] + sh, sc * yp[W + 1] + sh);
    out[idx] = pack_split(fmaxf(fmaxf(a, b), 0.f));
}

// --------------------------------- FC --------------------------------------
__global__ void fc1_partial_kernel(const uint32_t* __restrict__ x, const float* __restrict__ w,
                                   const float* __restrict__ scal, float* __restrict__ part,
                                   float* __restrict__ sp1, float* __restrict__ sp2) {
    __shared__ float s_w[64][33];
    __shared__ __align__(16) float s_x[32][34];
    __shared__ float r1[256], r2[256];
    const int K = 32768;
    const int o0 = blockIdx.x * 64;
    const int k0 = blockIdx.y * 2048;
    const int tid = threadIdx.x;
    const int tx = tid & 15;
    const int ty = tid >> 4;
    const float d = scal[0];

    float acc[4][2];
#pragma unroll
    for (int i = 0; i < 4; i++) { acc[i][0] = 0.f; acc[i][1] = 0.f; }
    float ms = 0.f, mc = 0.f;

    for (int kk = k0; kk < k0 + 2048; kk += 32) {
#pragma unroll
        for (int t = 0; t < 2; t++) {
            int idx = tid + t * 256;
            int row = idx >> 3, c4 = idx & 7;
            float4 v = *(const float4*)&w[(long)(o0 + row) * K + kk + c4 * 4];
            float a0 = fabsf(v.x), a1 = fabsf(v.y), a2 = fabsf(v.z), a3 = fabsf(v.w);
            if (a0 > d) { ms += a0; mc += 1.f; }
            if (a1 > d) { ms += a1; mc += 1.f; }
            if (a2 > d) { ms += a2; mc += 1.f; }
            if (a3 > d) { ms += a3; mc += 1.f; }
            s_w[row][c4 * 4 + 0] = (v.x > d) ? 1.f : ((v.x < -d) ? -1.f : 0.f);
            s_w[row][c4 * 4 + 1] = (v.y > d) ? 1.f : ((v.y < -d) ? -1.f : 0.f);
            s_w[row][c4 * 4 + 2] = (v.z > d) ? 1.f : ((v.z < -d) ? -1.f : 0.f);
            s_w[row][c4 * 4 + 3] = (v.w > d) ? 1.f : ((v.w < -d) ? -1.f : 0.f);
        }
        {
            int b = tid >> 3, c4 = tid & 7;
            uint4 u = *(const uint4*)&x[(long)b * K + kk + c4 * 4];
            s_x[c4 * 4 + 0][b] = unpack_split(u.x);
            s_x[c4 * 4 + 1][b] = unpack_split(u.y);
            s_x[c4 * 4 + 2][b] = unpack_split(u.z);
            s_x[c4 * 4 + 3][b] = unpack_split(u.w);
        }
        __syncthreads();
#pragma unroll
        for (int j = 0; j < 32; j++) {
            float2 xv = *(const float2*)&s_x[j][tx * 2];
#pragma unroll
            for (int i = 0; i < 4; i++) {
                float wv = s_w[ty * 4 + i][j];
                acc[i][0] += wv * xv.x;
                acc[i][1] += wv * xv.y;
            }
        }
        __syncthreads();
    }
#pragma unroll
    for (int i = 0; i < 4; i++)
#pragma unroll
        for (int q = 0; q < 2; q++)
            part[((long)blockIdx.y * 32 + tx * 2 + q) * 1024 + o0 + ty * 4 + i] = acc[i][q];

    r1[tid] = ms; r2[tid] = mc; __syncthreads();
    for (int o = 128; o > 0; o >>= 1) {
        if (tid < o) { r1[tid] += r1[tid + o]; r2[tid] += r2[tid + o]; }
        __syncthreads();
    }
    if (tid == 0) {
        int slot = blockIdx.y * 16 + blockIdx.x;
        sp1[slot] = r1[0];
        sp2[slot] = r2[0];
    }
}

__global__ void fc1_post_kernel(const float* __restrict__ part, const float* __restrict__ bias,
                                const float* __restrict__ scal, float* __restrict__ out) {
    int idx = blockIdx.x * 256 + threadIdx.x;
    if (idx >= 32 * 1024) return;
    int o = idx & 1023;
    float s = 0.f;
#pragma unroll
    for (int ks = 0; ks < 16; ks++) s += part[(long)ks * 32 * 1024 + idx];
    out[idx] = fmaxf(s * scal[1] + bias[o], 0.f);
}

__global__ void fc2_kernel(const float* __restrict__ x, const float* __restrict__ w,
                           const float* __restrict__ bias, const float* __restrict__ scal,
                           float* __restrict__ out) {
    int gw = (blockIdx.x * 256 + threadIdx.x) >> 5;
    int lane = threadIdx.x & 31;
    if (gw >= 32 * 1000) return;
    int b = gw / 1000, o = gw % 1000;
    const float d = scal[0];
    float a = 0.f;
    for (int k = lane; k < 1024; k += 32) {
        float wv = w[o * 1024 + k];
        float sg = (wv > d) ? 1.f : ((wv < -d) ? -1.f : 0.f);
        a += x[b * 1024 + k] * sg;
    }
#pragma unroll
    for (int off = 16; off; off >>= 1) a += __shfl_down_sync(0xffffffffu, a, off);
    if (lane == 0) out[b * 1000 + o] = a * scal[1] + bias[o];
}

// ------------------------------- host side ---------------------------------
static float* scal_slot(int slot) {
    float* sc;
    cudaGetSymbolAddress((void**)&sc, g_scal);
    return sc + 4 * slot;
}

static int stats_nb(long n) {
    long nb = (n + 4095) / 4096;
    if (nb > 512) nb = 512;
    if (nb < 1) nb = 1;
    return (int)nb;
}

static void bn_pool_tail(float* conv_buf, const float* gamma, const float* beta,
                         void* pool_buf, int CO, int nbx, int lw, int lhw, bool pack_out) {
    float *bp1, *bp2, *bsc, *bsh;
    cudaGetSymbolAddress((void**)&bp1, g_bnp1);
    cudaGetSymbolAddress((void**)&bp2, g_bnp2);
    cudaGetSymbolAddress((void**)&bsc, g_bnscale);
    cudaGetSymbolAddress((void**)&bsh, g_bnshift);
    const int N = N_BATCH << lhw;
    const int H = 1 << (lhw - lw), Wd = 1 << lw;
    bn_final_kernel<<<CO, 256>>>(bp1, bp2, nbx, 1.0f / (float)N, gamma, beta, bsc, bsh);
    long total = (long)N_BATCH * CO * (H / 2) * (Wd / 2);
    int pg = (int)((total + 255) / 256);
    if (pack_out)
        bn_relu_pool_p_kernel<<<pg, 256>>>(conv_buf, bsc, bsh, (uint32_t*)pool_buf, CO, H, Wd, total);
    else
        bn_relu_pool_h_kernel<<<pg, 256>>>(conv_buf, bsc, bsh, (uint16_t*)pool_buf, CO, H, Wd, total);
}

static void conv_split(const uint32_t* xin, const uint32_t* Apack, const float* gamma, const float* beta,
                       float* conv_buf, void* pool_buf, int CI, int CO, int nk, int lw, int lhw,
                       bool pack_out) {
    float *bp1, *bp2;
    cudaGetSymbolAddress((void**)&bp1, g_bnp1);
    cudaGetSymbolAddress((void**)&bp2, g_bnp2);
    const int N = N_BATCH << lhw;
    const int nbx = N / GNT;
    if (CO >= 128) {
        constexpr int MB = 128;
        size_t smem = (size_t)(2 * MB * T_LD + 2 * BB_BUF + MB * 8) * 4;
        cudaFuncSetAttribute(gemm_split_kernel<4>, cudaFuncAttributeMaxDynamicSharedMemorySize, (int)smem);
        gemm_split_kernel<4><<<dim3(nbx, CO / MB), 256, smem>>>(Apack, xin, conv_buf,
                                                                CI, nk, lw, lhw, N, nbx, bp1, bp2);
    } else {
        constexpr int MB = 64;
        size_t smem = (size_t)(2 * MB * T_LD + 2 * BB_BUF + MB * 8) * 4;
        cudaFuncSetAttribute(gemm_split_kernel<2>, cudaFuncAttributeMaxDynamicSharedMemorySize, (int)smem);
        gemm_split_kernel<2><<<dim3(nbx, CO / MB), 256, smem>>>(Apack, xin, conv_buf,
                                                                CI, nk, lw, lhw, N, nbx, bp1, bp2);
    }
    bn_pool_tail(conv_buf, gamma, beta, pool_buf, CO, nbx, lw, lhw, pack_out);
}

static void conv_h(const uint16_t* xin, const uint32_t* Apack, const float* gamma, const float* beta,
                   float* conv_buf, void* pool_buf, int CI, int CO, int nk, int lw, int lhw,
                   bool pack_out) {
    float *bp1, *bp2;
    cudaGetSymbolAddress((void**)&bp1, g_bnp1);
    cudaGetSymbolAddress((void**)&bp2, g_bnp2);
    const int N = N_BATCH << lhw;
    const int nbx = N / GNT;
    constexpr int MB = 128;
    size_t smem = (size_t)(2 * MB * T_LD + 2 * BB_BUF + MB * 8) * 4;
    cudaFuncSetAttribute(gemm_h_kernel<4>, cudaFuncAttributeMaxDynamicSharedMemorySize, (int)smem);
    gemm_h_kernel<4><<<dim3(nbx, CO / MB), 256, smem>>>(Apack, xin, conv_buf,
                                                        CI, nk, lw, lhw, N, nbx, bp1, bp2);
    bn_pool_tail(conv_buf, gamma, beta, pool_buf, CO, nbx, lw, lhw, pack_out);
}

extern "C" void kernel_launch(void* const* d_in, const int* in_sizes, int n_in,
                              void* d_out, int out_size) {
    const float* x   = (const float*)d_in[0];
    const float* w1  = (const float*)d_in[1];
    const float* g1  = (const float*)d_in[3];
    const float* be1 = (const float*)d_in[4];
    const float* w2  = (const float*)d_in[5];
    const float* g2  = (const float*)d_in[7];
    const float* be2 = (const float*)d_in[8];
    const float* w3  = (const float*)d_in[9];
    const float* g3  = (const float*)d_in[11];
    const float* be3 = (const float*)d_in[12];
    const float* w4  = (const float*)d_in[13];
    const float* g4  = (const float*)d_in[15];
    const float* be4 = (const float*)d_in[16];
    const float* fw1 = (const float*)d_in[17];
    const float* fb1 = (const float*)d_in[18];
    const float* fw2 = (const float*)d_in[19];
    const float* fb2 = (const float*)d_in[20];
    float* out = (float*)d_out;

    float *p_conv, *p_fc1, *p_fc1part, *p_sp1, *p_sp2, *p_cpart, *p_scal;
    uint16_t *p_pool;
    uint32_t *p_poolp, *p_pool4, *p_xpack, *pA1, *pA2, *pA3, *pA4;
    cudaGetSymbolAddress((void**)&p_conv, g_conv);
    cudaGetSymbolAddress((void**)&p_pool, g_pool);
    cudaGetSymbolAddress((void**)&p_poolp, g_poolp);
    cudaGetSymbolAddress((void**)&p_pool4, g_pool4);
    cudaGetSymbolAddress((void**)&p_xpack, g_xpack);
    cudaGetSymbolAddress((void**)&pA1, g_A1);
    cudaGetSymbolAddress((void**)&pA2, g_A2);
    cudaGetSymbolAddress((void**)&pA3, g_A3);
    cudaGetSymbolAddress((void**)&pA4, g_A4);
    cudaGetSymbolAddress((void**)&p_fc1, g_fc1);
    cudaGetSymbolAddress((void**)&p_fc1part, g_fc1part);
    cudaGetSymbolAddress((void**)&p_sp1, g_part1);
    cudaGetSymbolAddress((void**)&p_sp2, g_part2);
    cudaGetSymbolAddress((void**)&p_cpart, g_cpart);
    cudaGetSymbolAddress((void**)&p_scal, g_scal);

    // 1) conv-weight ternarize (batched; mixed pack formats)
    cw_abs_sum_kernel<<<dim3(CW_NB, 4), 256>>>(w1, w2, w3, w4, p_cpart);
    cw_delta_final_kernel<<<4, 128>>>(p_cpart, p_scal);
    cw_pack_kernel<<<1024, 256>>>(w1, w2, w3, w4, p_scal, pA1, pA2, pA3, pA4);

    // 2) FC deltas (float4 paths)
    {
        long n1 = (long)in_sizes[17];
        int nb1 = stats_nb(n1 / 4);
        abs_sum4_kernel<<<nb1, 256>>>((const float4*)fw1, n1 / 4, p_sp1);
        delta_final_kernel<<<1, 256>>>(p_sp1, nb1, 1.0f / (float)n1, scal_slot(4));
        long n2 = (long)in_sizes[19];
        int nb2 = stats_nb(n2 / 4);
        abs_sum4_kernel<<<nb2, 256>>>((const float4*)fw2, n2 / 4, p_sp1);
        delta_final_kernel<<<1, 256>>>(p_sp1, nb2, 1.0f / (float)n2, scal_slot(5));
        masked_sum4_kernel<<<nb2, 256>>>((const float4*)fw2, n2 / 4, scal_slot(5), p_sp1, p_sp2);
        alpha_final_kernel<<<1, 256>>>(p_sp1, p_sp2, nb2, scal_slot(5));
    }

    // 3) pack layer-1 input (split-bf16, 4 channels)
    pack_x_kernel<<<2097152 / 256, 256>>>(x, p_xpack);

    // 4) conv blocks: L1 split, L2/L3 fp16, L4 split
    conv_split(p_xpack, pA1, g1, be1, p_conv, p_pool,  4,   64,  1,  7, 14, false);
    conv_h    (p_pool,  pA2, g2, be2, p_conv, p_pool,  64,  128, 9,  6, 12, false);
    conv_h    (p_pool,  pA3, g3, be3, p_conv, p_poolp, 128, 256, 18, 5, 10, true);
    conv_split(p_poolp, pA4, g4, be4, p_conv, p_pool4, 256, 512, 72, 4, 8,  true);

    // 5) FC1 (split-K, inline ternarize + fused alpha stats) + alpha + relu
    fc1_partial_kernel<<<dim3(16, 16), 256>>>(p_pool4, fw1, scal_slot(4), p_fc1part, p_sp1, p_sp2);
    alpha_final_kernel<<<1, 256>>>(p_sp1, p_sp2, 256, scal_slot(4));
    fc1_post_kernel<<<(32 * 1024 + 255) / 256, 256>>>(p_fc1part, fb1, scal_slot(4), p_fc1);

    // 6) FC2 -> output
    fc2_kernel<<<(32 * 1000 * 32 + 255) / 256, 256>>>(p_fc1, fw2, fb2, scal_slot(5), out);
}